// round 10
// baseline (speedup 1.0000x reference)
#include <cuda_runtime.h>
#include <math.h>
#include <stdint.h>

#define NB 4
#define NL 4096
#define ND 256
#define BLD (NB*NL*ND)
#define SCALE 0.0625f
#define THR 512

// ---- scratch (static device globals; allocation is forbidden) ----
__device__ __align__(128) float g_qr[BLD], g_qi[BLD], g_kr[BLD], g_ki[BLD];
__device__ __align__(128) float g_vrt[BLD], g_vit[BLD];    // V transposed [b][d][tok]
__device__ __align__(128) float g_s[(size_t)NB*NL*NL];     // 268MB scores/probs

__device__ __forceinline__ float to_tf32(float x) {
    float y; asm("cvt.rna.tf32.f32 %0, %1;" : "=f"(y) : "f"(x)); return y;
}

#define MMA_TF32(c, a, b) \
    asm volatile("mma.sync.aligned.m16n8k8.row.col.f32.tf32.tf32.f32 " \
        "{%0,%1,%2,%3}, {%4,%5,%6,%7}, {%8,%9}, {%0,%1,%2,%3};" \
        : "+f"((c)[0]), "+f"((c)[1]), "+f"((c)[2]), "+f"((c)[3]) \
        : "r"((a)[0]), "r"((a)[1]), "r"((a)[2]), "r"((a)[3]), "r"((b)[0]), "r"((b)[1]))

#define CP_COMMIT asm volatile("cp.async.commit_group;" ::: "memory")
#define CP_WAIT2  asm volatile("cp.async.wait_group 2;" ::: "memory")
#define CP_WAIT1  asm volatile("cp.async.wait_group 1;" ::: "memory")
#define CP_WAIT0  asm volatile("cp.async.wait_group 0;" ::: "memory")

#define LDT 36                    // padded smem row stride (floats)
#define ATILE_F (128*LDT)         // 4608
#define BTILE_F (256*LDT)         // 9216
#define BUF_F (ATILE_F + BTILE_F) // 13824 floats per stage
#define NSTAGE 4
#define SMEM_BYTES (NSTAGE*BUF_F*4)   // 221184 B

// pipeline: need chunk ch done; committed groups = min(ch+3, CH)
#define PIPE_WAIT(ch, CH) do { \
    if ((ch) + 3 <= (CH)) CP_WAIT2; \
    else if ((ch) + 2 == (CH)) CP_WAIT1; \
    else CP_WAIT0; } while (0)

__device__ __forceinline__ uint32_t smem_u32(const void* p) {
    uint32_t a;
    asm("{ .reg .u64 t; cvta.to.shared.u64 t, %1; cvt.u32.u64 %0, t; }" : "=r"(a) : "l"(p));
    return a;
}

// ---- cp.async tile loaders, 512 threads ----
__device__ __forceinline__ void cpasyncA(uint32_t dstbase, const float* __restrict__ p,
                                         size_t ld, int tid) {       // 128x32
    #pragma unroll
    for (int i = 0; i < 2; i++) {
        int pos = tid + i*THR, row = pos >> 3, c4 = pos & 7;
        uint32_t dst = dstbase + (uint32_t)(row*LDT + c4*4)*4u;
        asm volatile("cp.async.cg.shared.global [%0], [%1], 16;"
                     :: "r"(dst), "l"(p + (size_t)row*ld + c4*4));
    }
}
__device__ __forceinline__ void cpasyncB(uint32_t dstbase, const float* __restrict__ p,
                                         size_t ld, int tid) {       // 256x32
    #pragma unroll
    for (int i = 0; i < 4; i++) {
        int pos = tid + i*THR, row = pos >> 3, c4 = pos & 7;
        uint32_t dst = dstbase + (uint32_t)(row*LDT + c4*4)*4u;
        asm volatile("cp.async.cg.shared.global [%0], [%1], 16;"
                     :: "r"(dst), "l"(p + (size_t)row*ld + c4*4));
    }
}

// ---- one 128x256x32 block step; warp tile 32x64; 16 warps (4m x 4n) ----
template<bool CVT>
__device__ __forceinline__ void mma_block(const float* As, const float* Bs,
                                          float c[2][8][4], int wm, int wn, int lane)
{
    const int g = lane >> 2, tg = lane & 3;
    #pragma unroll
    for (int k8 = 0; k8 < 4; k8++) {
        const int k0 = k8*8;
        uint32_t a[2][4];
        #pragma unroll
        for (int i = 0; i < 2; i++) {
            const float* ap = As + (wm + i*16 + g)*LDT + k0 + tg;
            float f0 = ap[0], f1 = ap[8*LDT], f2 = ap[4], f3 = ap[8*LDT + 4];
            if (CVT) { f0 = to_tf32(f0); f1 = to_tf32(f1); f2 = to_tf32(f2); f3 = to_tf32(f3); }
            a[i][0] = __float_as_uint(f0);
            a[i][1] = __float_as_uint(f1);
            a[i][2] = __float_as_uint(f2);
            a[i][3] = __float_as_uint(f3);
        }
        #pragma unroll
        for (int j = 0; j < 8; j++) {
            const float* bp = Bs + (wn + j*8 + g)*LDT + k0 + tg;
            float f0 = bp[0], f1 = bp[4];
            if (CVT) { f0 = to_tf32(f0); f1 = to_tf32(f1); }
            uint32_t b[2] = { __float_as_uint(f0), __float_as_uint(f1) };
            #pragma unroll
            for (int i = 0; i < 2; i++) MMA_TF32(c[i][j], a[i], b);
        }
    }
}

// generic epilogue (proj Q/K, scores).  ROUND: store tf32-rounded values.
template<bool ROUND>
__device__ __forceinline__ void epilogue(float c[2][8][4], float* __restrict__ out,
                                         size_t ldm, int m0, int n0, int wm, int wn,
                                         int lane, float scale, const float* __restrict__ bias)
{
    const int g = lane >> 2, tg = lane & 3;
    #pragma unroll
    for (int i = 0; i < 2; i++) {
        const int r0 = m0 + wm + i*16 + g;
        #pragma unroll
        for (int j = 0; j < 8; j++) {
            const int col = n0 + wn + j*8 + tg*2;
            float b0 = 0.f, b1 = 0.f;
            if (bias) { b0 = bias[col]; b1 = bias[col+1]; }
            float v00 = c[i][j][0]*scale + b0, v01 = c[i][j][1]*scale + b1;
            float v10 = c[i][j][2]*scale + b0, v11 = c[i][j][3]*scale + b1;
            if (ROUND) { v00 = to_tf32(v00); v01 = to_tf32(v01);
                         v10 = to_tf32(v10); v11 = to_tf32(v11); }
            *(float2*)&out[(size_t)r0*ldm + col]     = make_float2(v00, v01);
            *(float2*)&out[(size_t)(r0+8)*ldm + col] = make_float2(v10, v11);
        }
    }
}

// V epilogue: stage 128x256 tile in smem, store TRANSPOSED to Yt[d][tok].
// Yt points at this batch's [ND][NL] slab; tok0 = in-batch token base.
#define VST 257
__device__ __forceinline__ void vt_epilogue(float c[2][8][4], float* stg,
                                            const float* __restrict__ bias,
                                            float* __restrict__ Yt,
                                            int tok0, int wm, int wn, int lane, int wid)
{
    const int g = lane >> 2, tg = lane & 3;
    __syncthreads();                  // mainloop smem free
    #pragma unroll
    for (int i = 0; i < 2; i++) {
        const int r0 = wm + i*16 + g;
        #pragma unroll
        for (int j = 0; j < 8; j++) {
            const int col = wn + j*8 + tg*2;
            const float b0 = bias[col], b1 = bias[col+1];
            stg[r0*VST + col]       = to_tf32(c[i][j][0] + b0);
            stg[r0*VST + col+1]     = to_tf32(c[i][j][1] + b1);
            stg[(r0+8)*VST + col]   = to_tf32(c[i][j][2] + b0);
            stg[(r0+8)*VST + col+1] = to_tf32(c[i][j][3] + b1);
        }
    }
    __syncthreads();
    #pragma unroll
    for (int dd = 0; dd < 16; dd++) {
        const int d = wid*16 + dd;
        float4 v;
        v.x = stg[(lane*4+0)*VST + d];
        v.y = stg[(lane*4+1)*VST + d];
        v.z = stg[(lane*4+2)*VST + d];
        v.w = stg[(lane*4+3)*VST + d];
        *(float4*)&Yt[(size_t)d*NL + tok0 + lane*4] = v;
    }
}

// PV epilogue: cross-warp LayerNorm over 256 cols (128 rows), then store.
// smem layout (floats): sums [0,512), mean [512,640), rstd [640,768),
//                       gamma [768,1024), beta [1024,1280), squares [1536,2048)
__device__ __forceinline__ void ln_epilogue(float c[2][8][4], float* red,
                                            const float* __restrict__ gamma,
                                            const float* __restrict__ beta,
                                            float* __restrict__ Y,
                                            int wm, int wn, int lane, int tid, int wid)
{
    const int g = lane >> 2, tg = lane & 3;
    const int wg = wid & 3;           // n-column group 0..3
    __syncthreads();                  // main loop done; smem free
    if (tid < 256) { red[768 + tid] = gamma[tid]; red[1024 + tid] = beta[tid]; }
    #pragma unroll
    for (int i = 0; i < 2; i++) {
        const int rl = wm + i*16 + g;
        float s0 = 0.f, q0 = 0.f, s1 = 0.f, q1 = 0.f;
        #pragma unroll
        for (int j = 0; j < 8; j++) {
            s0 += c[i][j][0] + c[i][j][1];
            q0 += c[i][j][0]*c[i][j][0] + c[i][j][1]*c[i][j][1];
            s1 += c[i][j][2] + c[i][j][3];
            q1 += c[i][j][2]*c[i][j][2] + c[i][j][3]*c[i][j][3];
        }
        #pragma unroll
        for (int o = 1; o < 4; o <<= 1) {
            s0 += __shfl_xor_sync(0xffffffffu, s0, o);
            q0 += __shfl_xor_sync(0xffffffffu, q0, o);
            s1 += __shfl_xor_sync(0xffffffffu, s1, o);
            q1 += __shfl_xor_sync(0xffffffffu, q1, o);
        }
        if (tg == 0) {
            red[wg*128 + rl]         = s0; red[1536 + wg*128 + rl]     = q0;
            red[wg*128 + rl + 8]     = s1; red[1536 + wg*128 + rl + 8] = q1;
        }
    }
    __syncthreads();
    if (tid < 128) {
        float s = red[tid] + red[128+tid] + red[256+tid] + red[384+tid];
        float q = red[1536+tid] + red[1664+tid] + red[1792+tid] + red[1920+tid];
        float mean = s * (1.f/256.f);
        red[512 + tid] = mean;
        red[640 + tid] = rsqrtf(q * (1.f/256.f) - mean*mean + 1e-5f);
    }
    __syncthreads();
    #pragma unroll
    for (int i = 0; i < 2; i++) {
        const int rl = wm + i*16 + g;
        const float m0v = red[512 + rl],     rs0 = red[640 + rl];
        const float m1v = red[512 + rl + 8], rs1 = red[640 + rl + 8];
        #pragma unroll
        for (int j = 0; j < 8; j++) {
            const int col = wn + j*8 + tg*2;
            const float ga0 = red[768 + col],  ga1 = red[769 + col];
            const float be0 = red[1024 + col], be1 = red[1025 + col];
            float2 v0 = make_float2((c[i][j][0]-m0v)*rs0*ga0 + be0,
                                    (c[i][j][1]-m0v)*rs0*ga1 + be1);
            float2 v1 = make_float2((c[i][j][2]-m1v)*rs1*ga0 + be0,
                                    (c[i][j][3]-m1v)*rs1*ga1 + be1);
            *(float2*)&Y[(size_t)rl*ND + col]     = v0;
            *(float2*)&Y[(size_t)(rl+8)*ND + col] = v1;
        }
    }
}

// ============================================================
// Kernel 1: projections.  grid=(128, 6). block 128x256, K=256.
// ============================================================
__global__ __launch_bounds__(THR, 1) void proj_mma(
    const float* __restrict__ q_real, const float* __restrict__ q_imag,
    const float* __restrict__ k_real, const float* __restrict__ k_imag,
    const float* __restrict__ v_real, const float* __restrict__ v_imag,
    const float* __restrict__ Wq, const float* __restrict__ bq,
    const float* __restrict__ Wk, const float* __restrict__ bk,
    const float* __restrict__ Wv, const float* __restrict__ bv)
{
    extern __shared__ float smf[];
    const uint32_t sb = smem_u32(smf);
    const int tid = threadIdx.x, lane = tid & 31, wid = tid >> 5;
    const int wm = (wid >> 2)*32, wn = (wid & 3)*64;
    const int m0 = blockIdx.x*128, z = blockIdx.y;
    const float *X, *W, *bias; float* Y;
    switch (z) {
      case 0: X=q_real; W=Wq; bias=bq; Y=g_qr; break;
      case 1: X=q_imag; W=Wq; bias=bq; Y=g_qi; break;
      case 2: X=k_real; W=Wk; bias=bk; Y=g_kr; break;
      case 3: X=k_imag; W=Wk; bias=bk; Y=g_ki; break;
      case 4: X=v_real; W=Wv; bias=bv; Y=g_vrt; break;
      default: X=v_imag; W=Wv; bias=bv; Y=g_vit; break;
    }
    const float* Ab = X + (size_t)m0*ND;
    const int CH = 8;
    float c[2][8][4] = {};
    #pragma unroll
    for (int s = 0; s < 3; s++) {
        cpasyncA(sb + s*BUF_F*4, Ab + s*32, ND, tid);
        cpasyncB(sb + (s*BUF_F + ATILE_F)*4, W + s*32, ND, tid);
        CP_COMMIT;
    }
    #pragma unroll 1
    for (int ch = 0; ch < CH; ch++) {
        PIPE_WAIT(ch, CH);
        __syncthreads();
        if (ch + 3 < CH) {
            const int s = (ch+3) & 3;
            cpasyncA(sb + s*BUF_F*4, Ab + (ch+3)*32, ND, tid);
            cpasyncB(sb + (s*BUF_F + ATILE_F)*4, W + (ch+3)*32, ND, tid);
            CP_COMMIT;
        }
        float* base = smf + (ch & 3)*BUF_F;
        mma_block<true>(base, base + ATILE_F, c, wm, wn, lane);
    }
    if (z < 4) {
        epilogue<true>(c, Y, ND, m0, 0, wm, wn, lane, 1.f, bias);
    } else {
        const int b = m0 >> 12, tok0 = m0 & (NL - 1);
        vt_epilogue(c, smf, bias, Y + (size_t)b*ND*NL, tok0, wm, wn, lane, wid);
    }
}

// ============================================================
// Kernel 2: scores.  grid=(16, 32, 4). block 128x256, K=512
// ============================================================
__global__ __launch_bounds__(THR, 1) void scores_mma()
{
    extern __shared__ float smf[];
    const uint32_t sb = smem_u32(smf);
    const int tid = threadIdx.x, lane = tid & 31, wid = tid >> 5;
    const int wm = (wid >> 2)*32, wn = (wid & 3)*64;
    const int n0 = blockIdx.x*256, m0 = blockIdx.y*128, b = blockIdx.z;
    const float* APh[2] = { g_qr + (size_t)(b*NL + m0)*ND, g_qi + (size_t)(b*NL + m0)*ND };
    const float* BPh[2] = { g_kr + (size_t)(b*NL + n0)*ND, g_ki + (size_t)(b*NL + n0)*ND };
    const int CH = 16;
    float c[2][8][4] = {};
    #pragma unroll
    for (int s = 0; s < 3; s++) {
        cpasyncA(sb + s*BUF_F*4, APh[0] + s*32, ND, tid);
        cpasyncB(sb + (s*BUF_F + ATILE_F)*4, BPh[0] + s*32, ND, tid);
        CP_COMMIT;
    }
    #pragma unroll 1
    for (int ch = 0; ch < CH; ch++) {
        PIPE_WAIT(ch, CH);
        __syncthreads();
        if (ch + 3 < CH) {
            const int nc = ch + 3, s = nc & 3;
            cpasyncA(sb + s*BUF_F*4, APh[nc >> 3] + (nc & 7)*32, ND, tid);
            cpasyncB(sb + (s*BUF_F + ATILE_F)*4, BPh[nc >> 3] + (nc & 7)*32, ND, tid);
            CP_COMMIT;
        }
        float* base = smf + (ch & 3)*BUF_F;
        mma_block<false>(base, base + ATILE_F, c, wm, wn, lane);
    }
    epilogue<false>(c, g_s + (size_t)b*NL*NL, NL, m0, n0, wm, wn, lane, SCALE, nullptr);
}

// ============================================================
// Kernel 3: softmax with pad mask; writes probs tf32-rounded
// ============================================================
__global__ __launch_bounds__(256) void softmax_kernel(const unsigned char* __restrict__ mask)
{
    __shared__ float sh[8];
    const int row = blockIdx.x, b = row >> 12, t = threadIdx.x;
    float* S = g_s + (size_t)row * NL;
    const unsigned char* m = mask + (size_t)b * NL;
    float v[16];
    #pragma unroll
    for (int j = 0; j < 4; j++) {
        int f4 = t + j*256;
        float4 x = *(const float4*)&S[f4*4];
        uchar4 mk = *(const uchar4*)&m[f4*4];
        v[j*4+0] = mk.x ? -INFINITY : x.x;
        v[j*4+1] = mk.y ? -INFINITY : x.y;
        v[j*4+2] = mk.z ? -INFINITY : x.z;
        v[j*4+3] = mk.w ? -INFINITY : x.w;
    }
    float mx = -INFINITY;
    #pragma unroll
    for (int i = 0; i < 16; i++) mx = fmaxf(mx, v[i]);
    #pragma unroll
    for (int o = 16; o > 0; o >>= 1) mx = fmaxf(mx, __shfl_xor_sync(0xffffffffu, mx, o));
    if ((t & 31) == 0) sh[t >> 5] = mx;
    __syncthreads();
    mx = sh[0];
    #pragma unroll
    for (int i = 1; i < 8; i++) mx = fmaxf(mx, sh[i]);
    __syncthreads();
    float sum = 0.f;
    #pragma unroll
    for (int i = 0; i < 16; i++) { v[i] = __expf(v[i] - mx); sum += v[i]; }
    #pragma unroll
    for (int o = 16; o > 0; o >>= 1) sum += __shfl_xor_sync(0xffffffffu, sum, o);
    if ((t & 31) == 0) sh[t >> 5] = sum;
    __syncthreads();
    sum = 0.f;
    #pragma unroll
    for (int i = 0; i < 8; i++) sum += sh[i];
    const float inv = 1.f / sum;
    #pragma unroll
    for (int j = 0; j < 4; j++) {
        int f4 = t + j*256;
        float4 o;
        o.x = to_tf32(v[j*4+0]*inv); o.y = to_tf32(v[j*4+1]*inv);
        o.z = to_tf32(v[j*4+2]*inv); o.w = to_tf32(v[j*4+3]*inv);
        *(float4*)&S[f4*4] = o;
    }
}

// ============================================================
// Kernel 4: PV + fused LayerNorm.  grid=(2 streams, 32, 4). K=4096
// ============================================================
__global__ __launch_bounds__(THR, 1) void pv_mma(
    const float* __restrict__ gamma, const float* __restrict__ beta,
    float* __restrict__ out)
{
    extern __shared__ float smf[];
    const uint32_t sb = smem_u32(smf);
    const int tid = threadIdx.x, lane = tid & 31, wid = tid >> 5;
    const int wm = (wid >> 2)*32, wn = (wid & 3)*64;
    const int stream = blockIdx.x, m0 = blockIdx.y*128, b = blockIdx.z;
    const float* Ab = g_s + (size_t)(b*NL + m0)*NL;
    const float* Bb = (stream ? g_vit : g_vrt) + (size_t)b*ND*NL;
    float* Y = out + (size_t)stream*BLD + (size_t)(b*NL + m0)*ND;
    const int CH = 128;
    float c[2][8][4] = {};
    #pragma unroll
    for (int s = 0; s < 3; s++) {
        cpasyncA(sb + s*BUF_F*4, Ab + s*32, NL, tid);
        cpasyncB(sb + (s*BUF_F + ATILE_F)*4, Bb + s*32, NL, tid);
        CP_COMMIT;
    }
    #pragma unroll 1
    for (int ch = 0; ch < CH; ch++) {
        PIPE_WAIT(ch, CH);
        __syncthreads();
        if (ch + 3 < CH) {
            const int s = (ch+3) & 3;
            cpasyncA(sb + s*BUF_F*4, Ab + (ch+3)*32, NL, tid);
            cpasyncB(sb + (s*BUF_F + ATILE_F)*4, Bb + (ch+3)*32, NL, tid);
            CP_COMMIT;
        }
        float* base = smf + (ch & 3)*BUF_F;
        mma_block<false>(base, base + ATILE_F, c, wm, wn, lane);
    }
    ln_epilogue(c, smf, gamma, beta, Y, wm, wn, lane, tid, wid);
}

// ============================================================
extern "C" void kernel_launch(void* const* d_in, const int* in_sizes, int n_in,
                              void* d_out, int out_size)
{
    (void)in_sizes; (void)n_in; (void)out_size;
    const float* q_real = (const float*)d_in[0];
    const float* q_imag = (const float*)d_in[1];
    const float* k_real = (const float*)d_in[2];
    const float* k_imag = (const float*)d_in[3];
    const float* v_real = (const float*)d_in[4];
    const float* v_imag = (const float*)d_in[5];
    const unsigned char* pad_mask = (const unsigned char*)d_in[6];
    const float* Wq = (const float*)d_in[7];
    const float* bq = (const float*)d_in[8];
    const float* Wk = (const float*)d_in[9];
    const float* bk = (const float*)d_in[10];
    const float* Wv = (const float*)d_in[11];
    const float* bv = (const float*)d_in[12];
    const float* gamma = (const float*)d_in[13];
    const float* beta  = (const float*)d_in[14];
    float* out = (float*)d_out;

    cudaFuncSetAttribute(proj_mma,   cudaFuncAttributeMaxDynamicSharedMemorySize, SMEM_BYTES);
    cudaFuncSetAttribute(scores_mma, cudaFuncAttributeMaxDynamicSharedMemorySize, SMEM_BYTES);
    cudaFuncSetAttribute(pv_mma,     cudaFuncAttributeMaxDynamicSharedMemorySize, SMEM_BYTES);

    proj_mma<<<dim3(128, 6), THR, SMEM_BYTES>>>(q_real, q_imag, k_real, k_imag,
                                                v_real, v_imag, Wq, bq, Wk, bk, Wv, bv);
    scores_mma<<<dim3(16, 32, NB), THR, SMEM_BYTES>>>();
    softmax_kernel<<<NB*NL, 256>>>(pad_mask);
    pv_mma<<<dim3(2, 32, NB), THR, SMEM_BYTES>>>(gamma, beta, out);
}

// round 11
// speedup vs baseline: 1.2943x; 1.2943x over previous
#include <cuda_runtime.h>
#include <math.h>
#include <stdint.h>

#define NB 4
#define NL 4096
#define ND 256
#define BLD (NB*NL*ND)
#define SCALE 0.0625f

// ---- scratch (static device globals; allocation is forbidden) ----
__device__ __align__(128) float g_qr[BLD], g_qi[BLD], g_kr[BLD], g_ki[BLD];
__device__ __align__(128) float g_vrt[BLD], g_vit[BLD];    // V transposed [b][d][tok], tok perm
__device__ __align__(128) float g_s[(size_t)NB*NL*NL];     // 268MB scores/probs (cols perm)
__device__ unsigned char g_maskp[NB*NL];                   // permuted pad mask

// k-permutation within 8-groups: physical(l) = ((l&3)<<1)|((l>>2)&1)
// inverse:                       logical(p)  = ((p>>1)&3)|((p&1)<<2)

__device__ __forceinline__ float to_tf32(float x) {
    float y; asm("cvt.rna.tf32.f32 %0, %1;" : "=f"(y) : "f"(x)); return y;
}
__device__ __forceinline__ uint32_t smem_u32(const void* p) {
    uint32_t a;
    asm("{ .reg .u64 t; cvta.to.shared.u64 t, %1; cvt.u32.u64 %0, t; }" : "=r"(a) : "l"(p));
    return a;
}

#define MMA_TF32(c, a, b) \
    asm volatile("mma.sync.aligned.m16n8k8.row.col.f32.tf32.tf32.f32 " \
        "{%0,%1,%2,%3}, {%4,%5,%6,%7}, {%8,%9}, {%0,%1,%2,%3};" \
        : "+f"((c)[0]), "+f"((c)[1]), "+f"((c)[2]), "+f"((c)[3]) \
        : "r"((a)[0]), "r"((a)[1]), "r"((a)[2]), "r"((a)[3]), "r"((b)[0]), "r"((b)[1]))

#define CP_COMMIT asm volatile("cp.async.commit_group;" ::: "memory")
#define CP_WAIT2  asm volatile("cp.async.wait_group 2;" ::: "memory")
#define CP_WAIT1  asm volatile("cp.async.wait_group 1;" ::: "memory")
#define CP_WAIT0  asm volatile("cp.async.wait_group 0;" ::: "memory")

#define LDT 36                    // padded smem row stride (floats)
#define ATILE_F (128*LDT)         // 4608
#define BTILE_F (256*LDT)         // 9216
#define BUF_F (ATILE_F + BTILE_F) // 13824 floats per stage
#define NSTAGE 4
#define SMEM_BYTES (NSTAGE*BUF_F*4)   // 221184 B

#define PIPE_WAIT(ch, CH) do { \
    if ((ch) + 3 <= (CH)) CP_WAIT2; \
    else if ((ch) + 2 == (CH)) CP_WAIT1; \
    else CP_WAIT0; } while (0)

// ---- cp.async tile loaders, 256 threads ----
__device__ __forceinline__ void cpasyncA(uint32_t dstbase, const float* __restrict__ p,
                                         size_t ld, int tid) {       // 128x32
    #pragma unroll
    for (int i = 0; i < 4; i++) {
        int pos = tid + i*256, row = pos >> 3, c4 = pos & 7;
        uint32_t dst = dstbase + (uint32_t)(row*LDT + c4*4)*4u;
        asm volatile("cp.async.cg.shared.global [%0], [%1], 16;"
                     :: "r"(dst), "l"(p + (size_t)row*ld + c4*4));
    }
}
__device__ __forceinline__ void cpasyncB(uint32_t dstbase, const float* __restrict__ p,
                                         size_t ld, int tid) {       // 256x32
    #pragma unroll
    for (int i = 0; i < 8; i++) {
        int pos = tid + i*256, row = pos >> 3, c4 = pos & 7;
        uint32_t dst = dstbase + (uint32_t)(row*LDT + c4*4)*4u;
        asm volatile("cp.async.cg.shared.global [%0], [%1], 16;"
                     :: "r"(dst), "l"(p + (size_t)row*ld + c4*4));
    }
}

// ---- 128x256x32 block step; warp tile 64x64; RAW layout + cvt (proj only) ----
__device__ __forceinline__ void mma_block_raw(const float* As, const float* Bs,
                                              float c[4][8][4], int wm, int wn, int lane)
{
    const int g = lane >> 2, tg = lane & 3;
    #pragma unroll
    for (int k8 = 0; k8 < 4; k8++) {
        const int k0 = k8*8;
        uint32_t a[4][4];
        #pragma unroll
        for (int i = 0; i < 4; i++) {
            const float* ap = As + (wm + i*16 + g)*LDT + k0 + tg;
            a[i][0] = __float_as_uint(to_tf32(ap[0]));
            a[i][1] = __float_as_uint(to_tf32(ap[8*LDT]));
            a[i][2] = __float_as_uint(to_tf32(ap[4]));
            a[i][3] = __float_as_uint(to_tf32(ap[8*LDT + 4]));
        }
        #pragma unroll
        for (int j = 0; j < 8; j++) {
            const float* bp = Bs + (wn + j*8 + g)*LDT + k0 + tg;
            uint32_t b[2] = { __float_as_uint(to_tf32(bp[0])), __float_as_uint(to_tf32(bp[4])) };
            #pragma unroll
            for (int i = 0; i < 4; i++) MMA_TF32(c[i][j], a[i], b);
        }
    }
}

// ---- 128x256x32 block step; PERMUTED layout: float2 fragment loads ----
__device__ __forceinline__ void mma_block_perm(const float* As, const float* Bs,
                                               float c[4][8][4], int wm, int wn, int lane)
{
    const int g = lane >> 2, tg = lane & 3;
    #pragma unroll
    for (int k8 = 0; k8 < 4; k8++) {
        const int k0 = k8*8;
        uint32_t a[4][4];
        #pragma unroll
        for (int i = 0; i < 4; i++) {
            const float* ap = As + (wm + i*16 + g)*LDT + k0 + tg*2;
            float2 lo = *(const float2*)ap;
            float2 hi = *(const float2*)(ap + 8*LDT);
            a[i][0] = __float_as_uint(lo.x);   // logical k0+tg
            a[i][1] = __float_as_uint(hi.x);
            a[i][2] = __float_as_uint(lo.y);   // logical k0+tg+4
            a[i][3] = __float_as_uint(hi.y);
        }
        #pragma unroll
        for (int j = 0; j < 8; j++) {
            float2 bv = *(const float2*)(Bs + (wn + j*8 + g)*LDT + k0 + tg*2);
            uint32_t b[2] = { __float_as_uint(bv.x), __float_as_uint(bv.y) };
            #pragma unroll
            for (int i = 0; i < 4; i++) MMA_TF32(c[i][j], a[i], b);
        }
    }
}

// generic epilogue writing PERMUTED columns.  ROUND: tf32-round stored values.
template<bool ROUND>
__device__ __forceinline__ void epilogueP(float c[4][8][4], float* __restrict__ out,
                                          size_t ldm, int m0, int n0, int wm, int wn,
                                          int lane, float scale, const float* __restrict__ bias)
{
    const int g = lane >> 2, tg = lane & 3;
    #pragma unroll
    for (int i = 0; i < 4; i++) {
        const int r0 = m0 + wm + i*16 + g;
        #pragma unroll
        for (int j = 0; j < 8; j++) {
            const int col = n0 + wn + j*8 + tg*2;   // logical (even)
            const int p0 = (col & ~7) | ((col & 3) << 1) | ((col >> 2) & 1);
            const int c1 = col + 1;
            const int p1 = (c1 & ~7) | ((c1 & 3) << 1) | ((c1 >> 2) & 1);
            float b0 = 0.f, b1 = 0.f;
            if (bias) { b0 = bias[col]; b1 = bias[c1]; }
            float v00 = c[i][j][0]*scale + b0, v01 = c[i][j][1]*scale + b1;
            float v10 = c[i][j][2]*scale + b0, v11 = c[i][j][3]*scale + b1;
            if (ROUND) { v00 = to_tf32(v00); v01 = to_tf32(v01);
                         v10 = to_tf32(v10); v11 = to_tf32(v11); }
            out[(size_t)r0*ldm + p0]     = v00;
            out[(size_t)r0*ldm + p1]     = v01;
            out[(size_t)(r0+8)*ldm + p0] = v10;
            out[(size_t)(r0+8)*ldm + p1] = v11;
        }
    }
}

// V epilogue: stage 128x256 tile in smem, store TRANSPOSED to Yt[d][tok_phys].
#define VST 257
__device__ __forceinline__ void vt_epilogue(float c[4][8][4], float* stg,
                                            const float* __restrict__ bias,
                                            float* __restrict__ Yt,
                                            int tok0, int wm, int wn, int lane, int wid)
{
    const int g = lane >> 2, tg = lane & 3;
    __syncthreads();                  // mainloop smem free
    #pragma unroll
    for (int i = 0; i < 4; i++) {
        const int r0 = wm + i*16 + g;
        #pragma unroll
        for (int j = 0; j < 8; j++) {
            const int col = wn + j*8 + tg*2;
            const float b0 = bias[col], b1 = bias[col+1];
            stg[r0*VST + col]       = to_tf32(c[i][j][0] + b0);
            stg[r0*VST + col+1]     = to_tf32(c[i][j][1] + b1);
            stg[(r0+8)*VST + col]   = to_tf32(c[i][j][2] + b0);
            stg[(r0+8)*VST + col+1] = to_tf32(c[i][j][3] + b1);
        }
    }
    __syncthreads();
    #pragma unroll
    for (int dd = 0; dd < 32; dd++) {
        const int d = wid*32 + dd;
        float4 v;
        #pragma unroll
        for (int q = 0; q < 4; q++) {
            const int pp = lane*4 + q;                       // physical token slot (local)
            const int l = (pp & ~7) | ((pp >> 1) & 3) | ((pp & 1) << 2);  // logical token
            (&v.x)[q] = stg[l*VST + d];
        }
        *(float4*)&Yt[(size_t)d*NL + tok0 + lane*4] = v;
    }
}

// PV epilogue: cross-warp LayerNorm over 256 cols, then store (natural layout).
// smem floats: sums [0,512), squares [512,1024), mean [1024,1152), rstd [1152,1280),
//              gamma [1280,1536), beta [1536,1792)
__device__ __forceinline__ void ln_epilogue(float c[4][8][4], float* red,
                                            const float* __restrict__ gamma,
                                            const float* __restrict__ beta,
                                            float* __restrict__ Y,
                                            int wm, int wn, int lane, int tid, int wid)
{
    const int g = lane >> 2, tg = lane & 3;
    const int wg = wid >> 1;          // n-warp group 0..3
    __syncthreads();                  // main loop done; smem free
    red[1280 + tid] = gamma[tid];
    red[1536 + tid] = beta[tid];
    #pragma unroll
    for (int i = 0; i < 4; i++) {
        const int rl = wm + i*16 + g;
        float s0 = 0.f, q0 = 0.f, s1 = 0.f, q1 = 0.f;
        #pragma unroll
        for (int j = 0; j < 8; j++) {
            s0 += c[i][j][0] + c[i][j][1];
            q0 += c[i][j][0]*c[i][j][0] + c[i][j][1]*c[i][j][1];
            s1 += c[i][j][2] + c[i][j][3];
            q1 += c[i][j][2]*c[i][j][2] + c[i][j][3]*c[i][j][3];
        }
        #pragma unroll
        for (int o = 1; o < 4; o <<= 1) {
            s0 += __shfl_xor_sync(0xffffffffu, s0, o);
            q0 += __shfl_xor_sync(0xffffffffu, q0, o);
            s1 += __shfl_xor_sync(0xffffffffu, s1, o);
            q1 += __shfl_xor_sync(0xffffffffu, q1, o);
        }
        if (tg == 0) {
            red[wg*128 + rl]       = s0; red[512 + wg*128 + rl]     = q0;
            red[wg*128 + rl + 8]   = s1; red[512 + wg*128 + rl + 8] = q1;
        }
    }
    __syncthreads();
    if (tid < 128) {
        float s = red[tid] + red[128+tid] + red[256+tid] + red[384+tid];
        float q = red[512+tid] + red[640+tid] + red[768+tid] + red[896+tid];
        float mean = s * (1.f/256.f);
        red[1024 + tid] = mean;
        red[1152 + tid] = rsqrtf(q * (1.f/256.f) - mean*mean + 1e-5f);
    }
    __syncthreads();
    #pragma unroll
    for (int i = 0; i < 4; i++) {
        const int rl = wm + i*16 + g;
        const float m0v = red[1024 + rl],     rs0 = red[1152 + rl];
        const float m1v = red[1024 + rl + 8], rs1 = red[1152 + rl + 8];
        #pragma unroll
        for (int j = 0; j < 8; j++) {
            const int col = wn + j*8 + tg*2;
            const float ga0 = red[1280 + col], ga1 = red[1281 + col];
            const float be0 = red[1536 + col], be1 = red[1537 + col];
            float2 v0 = make_float2((c[i][j][0]-m0v)*rs0*ga0 + be0,
                                    (c[i][j][1]-m0v)*rs0*ga1 + be1);
            float2 v1 = make_float2((c[i][j][2]-m1v)*rs1*ga0 + be0,
                                    (c[i][j][3]-m1v)*rs1*ga1 + be1);
            *(float2*)&Y[(size_t)rl*ND + col]     = v0;
            *(float2*)&Y[(size_t)(rl+8)*ND + col] = v1;
        }
    }
}

// ============================================================
// Kernel 0: permute pad mask into g_maskp
// ============================================================
__global__ __launch_bounds__(256) void mask_perm(const unsigned char* __restrict__ m)
{
    const int i = blockIdx.x*256 + threadIdx.x;          // 0..16383
    const int p = (i & ~7) | ((i & 3) << 1) | ((i >> 2) & 1);
    g_maskp[p] = m[i];
}

// ============================================================
// Kernel 1: projections.  grid=(128, 6). block 128x256, K=256.
// Raw inputs -> cvt in fragments; Q/K stored feature-permuted;
// V stored transposed with token-permutation.
// ============================================================
__global__ __launch_bounds__(256, 1) void proj_mma(
    const float* __restrict__ q_real, const float* __restrict__ q_imag,
    const float* __restrict__ k_real, const float* __restrict__ k_imag,
    const float* __restrict__ v_real, const float* __restrict__ v_imag,
    const float* __restrict__ Wq, const float* __restrict__ bq,
    const float* __restrict__ Wk, const float* __restrict__ bk,
    const float* __restrict__ Wv, const float* __restrict__ bv)
{
    extern __shared__ float smf[];
    const uint32_t sb = smem_u32(smf);
    const int tid = threadIdx.x, lane = tid & 31, wid = tid >> 5;
    const int wm = (wid & 1)*64, wn = (wid >> 1)*64;
    const int m0 = blockIdx.x*128, z = blockIdx.y;
    const float *X, *W, *bias; float* Y;
    switch (z) {
      case 0: X=q_real; W=Wq; bias=bq; Y=g_qr; break;
      case 1: X=q_imag; W=Wq; bias=bq; Y=g_qi; break;
      case 2: X=k_real; W=Wk; bias=bk; Y=g_kr; break;
      case 3: X=k_imag; W=Wk; bias=bk; Y=g_ki; break;
      case 4: X=v_real; W=Wv; bias=bv; Y=g_vrt; break;
      default: X=v_imag; W=Wv; bias=bv; Y=g_vit; break;
    }
    const float* Ab = X + (size_t)m0*ND;
    const int CH = 8;
    float c[4][8][4] = {};
    #pragma unroll
    for (int s = 0; s < 3; s++) {
        cpasyncA(sb + s*BUF_F*4, Ab + s*32, ND, tid);
        cpasyncB(sb + (s*BUF_F + ATILE_F)*4, W + s*32, ND, tid);
        CP_COMMIT;
    }
    #pragma unroll 1
    for (int ch = 0; ch < CH; ch++) {
        PIPE_WAIT(ch, CH);
        __syncthreads();
        if (ch + 3 < CH) {
            const int s = (ch+3) & 3;
            cpasyncA(sb + s*BUF_F*4, Ab + (ch+3)*32, ND, tid);
            cpasyncB(sb + (s*BUF_F + ATILE_F)*4, W + (ch+3)*32, ND, tid);
            CP_COMMIT;
        }
        float* base = smf + (ch & 3)*BUF_F;
        mma_block_raw(base, base + ATILE_F, c, wm, wn, lane);
    }
    if (z < 4) {
        epilogueP<true>(c, Y, ND, m0, 0, wm, wn, lane, 1.f, bias);
    } else {
        const int b = m0 >> 12, tok0 = m0 & (NL - 1);
        vt_epilogue(c, smf, bias, Y + (size_t)b*ND*NL, tok0, wm, wn, lane, wid);
    }
}

// ============================================================
// Kernel 2: scores.  grid=(16, 32, 4). block 128x256, K=512.
// Operands feature-permuted -> float2 fragment loads; output cols permuted.
// ============================================================
__global__ __launch_bounds__(256, 1) void scores_mma()
{
    extern __shared__ float smf[];
    const uint32_t sb = smem_u32(smf);
    const int tid = threadIdx.x, lane = tid & 31, wid = tid >> 5;
    const int wm = (wid & 1)*64, wn = (wid >> 1)*64;
    const int n0 = blockIdx.x*256, m0 = blockIdx.y*128, b = blockIdx.z;
    const float* APh[2] = { g_qr + (size_t)(b*NL + m0)*ND, g_qi + (size_t)(b*NL + m0)*ND };
    const float* BPh[2] = { g_kr + (size_t)(b*NL + n0)*ND, g_ki + (size_t)(b*NL + n0)*ND };
    const int CH = 16;
    float c[4][8][4] = {};
    #pragma unroll
    for (int s = 0; s < 3; s++) {
        cpasyncA(sb + s*BUF_F*4, APh[0] + s*32, ND, tid);
        cpasyncB(sb + (s*BUF_F + ATILE_F)*4, BPh[0] + s*32, ND, tid);
        CP_COMMIT;
    }
    #pragma unroll 1
    for (int ch = 0; ch < CH; ch++) {
        PIPE_WAIT(ch, CH);
        __syncthreads();
        if (ch + 3 < CH) {
            const int nc = ch + 3, s = nc & 3;
            cpasyncA(sb + s*BUF_F*4, APh[nc >> 3] + (nc & 7)*32, ND, tid);
            cpasyncB(sb + (s*BUF_F + ATILE_F)*4, BPh[nc >> 3] + (nc & 7)*32, ND, tid);
            CP_COMMIT;
        }
        float* base = smf + (ch & 3)*BUF_F;
        mma_block_perm(base, base + ATILE_F, c, wm, wn, lane);
    }
    epilogueP<false>(c, g_s + (size_t)b*NL*NL, NL, m0, n0, wm, wn, lane, SCALE, nullptr);
}

// ============================================================
// Kernel 3: softmax with PERMUTED pad mask; writes probs tf32-rounded
// (row reductions are permutation-invariant)
// ============================================================
__global__ __launch_bounds__(256) void softmax_kernel()
{
    __shared__ float sh[8];
    const int row = blockIdx.x, b = row >> 12, t = threadIdx.x;
    float* S = g_s + (size_t)row * NL;
    const unsigned char* m = g_maskp + (size_t)b * NL;
    float v[16];
    #pragma unroll
    for (int j = 0; j < 4; j++) {
        int f4 = t + j*256;
        float4 x = *(const float4*)&S[f4*4];
        uchar4 mk = *(const uchar4*)&m[f4*4];
        v[j*4+0] = mk.x ? -INFINITY : x.x;
        v[j*4+1] = mk.y ? -INFINITY : x.y;
        v[j*4+2] = mk.z ? -INFINITY : x.z;
        v[j*4+3] = mk.w ? -INFINITY : x.w;
    }
    float mx = -INFINITY;
    #pragma unroll
    for (int i = 0; i < 16; i++) mx = fmaxf(mx, v[i]);
    #pragma unroll
    for (int o = 16; o > 0; o >>= 1) mx = fmaxf(mx, __shfl_xor_sync(0xffffffffu, mx, o));
    if ((t & 31) == 0) sh[t >> 5] = mx;
    __syncthreads();
    mx = sh[0];
    #pragma unroll
    for (int i = 1; i < 8; i++) mx = fmaxf(mx, sh[i]);
    __syncthreads();
    float sum = 0.f;
    #pragma unroll
    for (int i = 0; i < 16; i++) { v[i] = __expf(v[i] - mx); sum += v[i]; }
    #pragma unroll
    for (int o = 16; o > 0; o >>= 1) sum += __shfl_xor_sync(0xffffffffu, sum, o);
    if ((t & 31) == 0) sh[t >> 5] = sum;
    __syncthreads();
    sum = 0.f;
    #pragma unroll
    for (int i = 0; i < 8; i++) sum += sh[i];
    const float inv = 1.f / sum;
    #pragma unroll
    for (int j = 0; j < 4; j++) {
        int f4 = t + j*256;
        float4 o;
        o.x = to_tf32(v[j*4+0]*inv); o.y = to_tf32(v[j*4+1]*inv);
        o.z = to_tf32(v[j*4+2]*inv); o.w = to_tf32(v[j*4+3]*inv);
        *(float4*)&S[f4*4] = o;
    }
}

// ============================================================
// Kernel 4: PV + fused LayerNorm.  grid=(2 streams, 32, 4). K=4096.
// P cols and Vt tokens share the same permutation -> aligned k.
// ============================================================
__global__ __launch_bounds__(256, 1) void pv_mma(
    const float* __restrict__ gamma, const float* __restrict__ beta,
    float* __restrict__ out)
{
    extern __shared__ float smf[];
    const uint32_t sb = smem_u32(smf);
    const int tid = threadIdx.x, lane = tid & 31, wid = tid >> 5;
    const int wm = (wid & 1)*64, wn = (wid >> 1)*64;
    const int stream = blockIdx.x, m0 = blockIdx.y*128, b = blockIdx.z;
    const float* Ab = g_s + (size_t)(b*NL + m0)*NL;
    const float* Bb = (stream ? g_vit : g_vrt) + (size_t)b*ND*NL;
    float* Y = out + (size_t)stream*BLD + (size_t)(b*NL + m0)*ND;
    const int CH = 128;
    float c[4][8][4] = {};
    #pragma unroll
    for (int s = 0; s < 3; s++) {
        cpasyncA(sb + s*BUF_F*4, Ab + s*32, NL, tid);
        cpasyncB(sb + (s*BUF_F + ATILE_F)*4, Bb + s*32, NL, tid);
        CP_COMMIT;
    }
    #pragma unroll 1
    for (int ch = 0; ch < CH; ch++) {
        PIPE_WAIT(ch, CH);
        __syncthreads();
        if (ch + 3 < CH) {
            const int s = (ch+3) & 3;
            cpasyncA(sb + s*BUF_F*4, Ab + (ch+3)*32, NL, tid);
            cpasyncB(sb + (s*BUF_F + ATILE_F)*4, Bb + (ch+3)*32, NL, tid);
            CP_COMMIT;
        }
        float* base = smf + (ch & 3)*BUF_F;
        mma_block_perm(base, base + ATILE_F, c, wm, wn, lane);
    }
    ln_epilogue(c, smf, gamma, beta, Y, wm, wn, lane, tid, wid);
}

// ============================================================
extern "C" void kernel_launch(void* const* d_in, const int* in_sizes, int n_in,
                              void* d_out, int out_size)
{
    (void)in_sizes; (void)n_in; (void)out_size;
    const float* q_real = (const float*)d_in[0];
    const float* q_imag = (const float*)d_in[1];
    const float* k_real = (const float*)d_in[2];
    const float* k_imag = (const float*)d_in[3];
    const float* v_real = (const float*)d_in[4];
    const float* v_imag = (const float*)d_in[5];
    const unsigned char* pad_mask = (const unsigned char*)d_in[6];
    const float* Wq = (const float*)d_in[7];
    const float* bq = (const float*)d_in[8];
    const float* Wk = (const float*)d_in[9];
    const float* bk = (const float*)d_in[10];
    const float* Wv = (const float*)d_in[11];
    const float* bv = (const float*)d_in[12];
    const float* gamma = (const float*)d_in[13];
    const float* beta  = (const float*)d_in[14];
    float* out = (float*)d_out;

    cudaFuncSetAttribute(proj_mma,   cudaFuncAttributeMaxDynamicSharedMemorySize, SMEM_BYTES);
    cudaFuncSetAttribute(scores_mma, cudaFuncAttributeMaxDynamicSharedMemorySize, SMEM_BYTES);
    cudaFuncSetAttribute(pv_mma,     cudaFuncAttributeMaxDynamicSharedMemorySize, SMEM_BYTES);

    mask_perm<<<NB*NL/256, 256>>>(pad_mask);
    proj_mma<<<dim3(128, 6), 256, SMEM_BYTES>>>(q_real, q_imag, k_real, k_imag,
                                                v_real, v_imag, Wq, bq, Wk, bk, Wv, bv);
    scores_mma<<<dim3(16, 32, NB), 256, SMEM_BYTES>>>();
    softmax_kernel<<<NB*NL, 256>>>();
    pv_mma<<<dim3(2, 32, NB), 256, SMEM_BYTES>>>(gamma, beta, out);
}

// round 12
// speedup vs baseline: 1.4584x; 1.1268x over previous
#include <cuda_runtime.h>
#include <math.h>
#include <stdint.h>

#define NB 4
#define NL 4096
#define ND 256
#define BLD (NB*NL*ND)
#define SCALE 0.0625f

// ---- scratch (static device globals; allocation is forbidden) ----
__device__ __align__(128) float g_qr[BLD], g_qi[BLD], g_kr[BLD], g_ki[BLD];
__device__ __align__(128) float g_vrt[BLD], g_vit[BLD];    // V transposed [b][d][tok], tok perm
__device__ __align__(128) float g_s[(size_t)NB*NL*NL];     // 268MB scores/probs (cols perm)
__device__ unsigned char g_maskp[NB*NL];                   // permuted pad mask

// k-permutation within 8-groups: physical(l) = ((l&3)<<1)|((l>>2)&1)
// inverse:                       logical(p)  = ((p>>1)&3)|((p&1)<<2)

__device__ __forceinline__ float to_tf32(float x) {
    float y; asm("cvt.rna.tf32.f32 %0, %1;" : "=f"(y) : "f"(x)); return y;
}
__device__ __forceinline__ uint32_t smem_u32(const void* p) {
    uint32_t a;
    asm("{ .reg .u64 t; cvta.to.shared.u64 t, %1; cvt.u32.u64 %0, t; }" : "=r"(a) : "l"(p));
    return a;
}

#define MMA_TF32(c, a, b) \
    asm volatile("mma.sync.aligned.m16n8k8.row.col.f32.tf32.tf32.f32 " \
        "{%0,%1,%2,%3}, {%4,%5,%6,%7}, {%8,%9}, {%0,%1,%2,%3};" \
        : "+f"((c)[0]), "+f"((c)[1]), "+f"((c)[2]), "+f"((c)[3]) \
        : "r"((a)[0]), "r"((a)[1]), "r"((a)[2]), "r"((a)[3]), "r"((b)[0]), "r"((b)[1]))

#define CP_COMMIT asm volatile("cp.async.commit_group;" ::: "memory")
#define CP_WAIT2  asm volatile("cp.async.wait_group 2;" ::: "memory")
#define CP_WAIT1  asm volatile("cp.async.wait_group 1;" ::: "memory")
#define CP_WAIT0  asm volatile("cp.async.wait_group 0;" ::: "memory")

// ---- proj (scalar path): LDT 36, 4 stages ----
#define LDT_P 36
#define ATILE_P (128*LDT_P)          // 4608
#define BTILE_P (256*LDT_P)          // 9216
#define BUF_P (ATILE_P + BTILE_P)    // 13824
#define SMEM_P (4*BUF_P*4)           // 221184 B

// ---- scores/pv (float2 path): LDT 40 (conflict-free for LDS.64), 3 stages ----
#define LDT_G 40
#define ATILE_G (128*LDT_G)          // 5120
#define BTILE_G (256*LDT_G)          // 10240
#define BUF_G (ATILE_G + BTILE_G)    // 15360
#define SMEM_G (3*BUF_G*4)           // 184320 B

// 4-stage distance-3 wait (proj)
#define PIPE_WAIT4(ch, CH) do { \
    if ((ch) + 3 <= (CH)) CP_WAIT2; \
    else if ((ch) + 2 == (CH)) CP_WAIT1; \
    else CP_WAIT0; } while (0)
// 3-stage distance-2 wait (scores/pv)
#define PIPE_WAIT3(ch, CH) do { \
    if ((ch) + 1 < (CH)) CP_WAIT1; else CP_WAIT0; } while (0)

// ---- cp.async tile loaders, 256 threads, parametric LDT ----
template<int LDT>
__device__ __forceinline__ void cpasyncA(uint32_t dstbase, const float* __restrict__ p,
                                         size_t ld, int tid) {       // 128x32
    #pragma unroll
    for (int i = 0; i < 4; i++) {
        int pos = tid + i*256, row = pos >> 3, c4 = pos & 7;
        uint32_t dst = dstbase + (uint32_t)(row*LDT + c4*4)*4u;
        asm volatile("cp.async.cg.shared.global [%0], [%1], 16;"
                     :: "r"(dst), "l"(p + (size_t)row*ld + c4*4));
    }
}
template<int LDT>
__device__ __forceinline__ void cpasyncB(uint32_t dstbase, const float* __restrict__ p,
                                         size_t ld, int tid) {       // 256x32
    #pragma unroll
    for (int i = 0; i < 8; i++) {
        int pos = tid + i*256, row = pos >> 3, c4 = pos & 7;
        uint32_t dst = dstbase + (uint32_t)(row*LDT + c4*4)*4u;
        asm volatile("cp.async.cg.shared.global [%0], [%1], 16;"
                     :: "r"(dst), "l"(p + (size_t)row*ld + c4*4));
    }
}

// ---- 128x256x32 block step; warp tile 64x64; RAW layout + cvt (proj) ----
__device__ __forceinline__ void mma_block_raw(const float* As, const float* Bs,
                                              float c[4][8][4], int wm, int wn, int lane)
{
    const int g = lane >> 2, tg = lane & 3;
    #pragma unroll
    for (int k8 = 0; k8 < 4; k8++) {
        const int k0 = k8*8;
        uint32_t a[4][4];
        #pragma unroll
        for (int i = 0; i < 4; i++) {
            const float* ap = As + (wm + i*16 + g)*LDT_P + k0 + tg;
            a[i][0] = __float_as_uint(to_tf32(ap[0]));
            a[i][1] = __float_as_uint(to_tf32(ap[8*LDT_P]));
            a[i][2] = __float_as_uint(to_tf32(ap[4]));
            a[i][3] = __float_as_uint(to_tf32(ap[8*LDT_P + 4]));
        }
        #pragma unroll
        for (int j = 0; j < 8; j++) {
            const float* bp = Bs + (wn + j*8 + g)*LDT_P + k0 + tg;
            uint32_t b[2] = { __float_as_uint(to_tf32(bp[0])), __float_as_uint(to_tf32(bp[4])) };
            #pragma unroll
            for (int i = 0; i < 4; i++) MMA_TF32(c[i][j], a[i], b);
        }
    }
}

// ---- 128x256x32 block step; PERMUTED layout: conflict-free float2 loads ----
__device__ __forceinline__ void mma_block_perm(const float* As, const float* Bs,
                                               float c[4][8][4], int wm, int wn, int lane)
{
    const int g = lane >> 2, tg = lane & 3;
    #pragma unroll
    for (int k8 = 0; k8 < 4; k8++) {
        const int k0 = k8*8;
        uint32_t a[4][4];
        #pragma unroll
        for (int i = 0; i < 4; i++) {
            const float* ap = As + (wm + i*16 + g)*LDT_G + k0 + tg*2;
            float2 lo = *(const float2*)ap;
            float2 hi = *(const float2*)(ap + 8*LDT_G);
            a[i][0] = __float_as_uint(lo.x);   // logical k0+tg
            a[i][1] = __float_as_uint(hi.x);
            a[i][2] = __float_as_uint(lo.y);   // logical k0+tg+4
            a[i][3] = __float_as_uint(hi.y);
        }
        #pragma unroll
        for (int j = 0; j < 8; j++) {
            float2 bv = *(const float2*)(Bs + (wn + j*8 + g)*LDT_G + k0 + tg*2);
            uint32_t b[2] = { __float_as_uint(bv.x), __float_as_uint(bv.y) };
            #pragma unroll
            for (int i = 0; i < 4; i++) MMA_TF32(c[i][j], a[i], b);
        }
    }
}

// generic epilogue writing PERMUTED columns.  ROUND: tf32-round stored values.
template<bool ROUND>
__device__ __forceinline__ void epilogueP(float c[4][8][4], float* __restrict__ out,
                                          size_t ldm, int m0, int n0, int wm, int wn,
                                          int lane, float scale, const float* __restrict__ bias)
{
    const int g = lane >> 2, tg = lane & 3;
    #pragma unroll
    for (int i = 0; i < 4; i++) {
        const int r0 = m0 + wm + i*16 + g;
        #pragma unroll
        for (int j = 0; j < 8; j++) {
            const int col = n0 + wn + j*8 + tg*2;   // logical (even)
            const int p0 = (col & ~7) | ((col & 3) << 1) | ((col >> 2) & 1);
            const int c1 = col + 1;
            const int p1 = (c1 & ~7) | ((c1 & 3) << 1) | ((c1 >> 2) & 1);
            float b0 = 0.f, b1 = 0.f;
            if (bias) { b0 = bias[col]; b1 = bias[c1]; }
            float v00 = c[i][j][0]*scale + b0, v01 = c[i][j][1]*scale + b1;
            float v10 = c[i][j][2]*scale + b0, v11 = c[i][j][3]*scale + b1;
            if (ROUND) { v00 = to_tf32(v00); v01 = to_tf32(v01);
                         v10 = to_tf32(v10); v11 = to_tf32(v11); }
            out[(size_t)r0*ldm + p0]     = v00;
            out[(size_t)r0*ldm + p1]     = v01;
            out[(size_t)(r0+8)*ldm + p0] = v10;
            out[(size_t)(r0+8)*ldm + p1] = v11;
        }
    }
}

// V epilogue: stage 128x256 tile in smem, store TRANSPOSED to Yt[d][tok_phys].
#define VST 257
__device__ __forceinline__ void vt_epilogue(float c[4][8][4], float* stg,
                                            const float* __restrict__ bias,
                                            float* __restrict__ Yt,
                                            int tok0, int wm, int wn, int lane, int wid)
{
    const int g = lane >> 2, tg = lane & 3;
    __syncthreads();                  // mainloop smem free
    #pragma unroll
    for (int i = 0; i < 4; i++) {
        const int r0 = wm + i*16 + g;
        #pragma unroll
        for (int j = 0; j < 8; j++) {
            const int col = wn + j*8 + tg*2;
            const float b0 = bias[col], b1 = bias[col+1];
            stg[r0*VST + col]       = to_tf32(c[i][j][0] + b0);
            stg[r0*VST + col+1]     = to_tf32(c[i][j][1] + b1);
            stg[(r0+8)*VST + col]   = to_tf32(c[i][j][2] + b0);
            stg[(r0+8)*VST + col+1] = to_tf32(c[i][j][3] + b1);
        }
    }
    __syncthreads();
    #pragma unroll
    for (int dd = 0; dd < 32; dd++) {
        const int d = wid*32 + dd;
        float4 v;
        #pragma unroll
        for (int q = 0; q < 4; q++) {
            const int pp = lane*4 + q;                       // physical token slot (local)
            const int l = (pp & ~7) | ((pp >> 1) & 3) | ((pp & 1) << 2);  // logical token
            (&v.x)[q] = stg[l*VST + d];
        }
        *(float4*)&Yt[(size_t)d*NL + tok0 + lane*4] = v;
    }
}

// PV epilogue: cross-warp LayerNorm over 256 cols, then store (natural layout).
__device__ __forceinline__ void ln_epilogue(float c[4][8][4], float* red,
                                            const float* __restrict__ gamma,
                                            const float* __restrict__ beta,
                                            float* __restrict__ Y,
                                            int wm, int wn, int lane, int tid, int wid)
{
    const int g = lane >> 2, tg = lane & 3;
    const int wg = wid >> 1;          // n-warp group 0..3
    __syncthreads();                  // main loop done; smem free
    red[1280 + tid] = gamma[tid];
    red[1536 + tid] = beta[tid];
    #pragma unroll
    for (int i = 0; i < 4; i++) {
        const int rl = wm + i*16 + g;
        float s0 = 0.f, q0 = 0.f, s1 = 0.f, q1 = 0.f;
        #pragma unroll
        for (int j = 0; j < 8; j++) {
            s0 += c[i][j][0] + c[i][j][1];
            q0 += c[i][j][0]*c[i][j][0] + c[i][j][1]*c[i][j][1];
            s1 += c[i][j][2] + c[i][j][3];
            q1 += c[i][j][2]*c[i][j][2] + c[i][j][3]*c[i][j][3];
        }
        #pragma unroll
        for (int o = 1; o < 4; o <<= 1) {
            s0 += __shfl_xor_sync(0xffffffffu, s0, o);
            q0 += __shfl_xor_sync(0xffffffffu, q0, o);
            s1 += __shfl_xor_sync(0xffffffffu, s1, o);
            q1 += __shfl_xor_sync(0xffffffffu, q1, o);
        }
        if (tg == 0) {
            red[wg*128 + rl]       = s0; red[512 + wg*128 + rl]     = q0;
            red[wg*128 + rl + 8]   = s1; red[512 + wg*128 + rl + 8] = q1;
        }
    }
    __syncthreads();
    if (tid < 128) {
        float s = red[tid] + red[128+tid] + red[256+tid] + red[384+tid];
        float q = red[512+tid] + red[640+tid] + red[768+tid] + red[896+tid];
        float mean = s * (1.f/256.f);
        red[1024 + tid] = mean;
        red[1152 + tid] = rsqrtf(q * (1.f/256.f) - mean*mean + 1e-5f);
    }
    __syncthreads();
    #pragma unroll
    for (int i = 0; i < 4; i++) {
        const int rl = wm + i*16 + g;
        const float m0v = red[1024 + rl],     rs0 = red[1152 + rl];
        const float m1v = red[1024 + rl + 8], rs1 = red[1152 + rl + 8];
        #pragma unroll
        for (int j = 0; j < 8; j++) {
            const int col = wn + j*8 + tg*2;
            const float ga0 = red[1280 + col], ga1 = red[1281 + col];
            const float be0 = red[1536 + col], be1 = red[1537 + col];
            float2 v0 = make_float2((c[i][j][0]-m0v)*rs0*ga0 + be0,
                                    (c[i][j][1]-m0v)*rs0*ga1 + be1);
            float2 v1 = make_float2((c[i][j][2]-m1v)*rs1*ga0 + be0,
                                    (c[i][j][3]-m1v)*rs1*ga1 + be1);
            *(float2*)&Y[(size_t)rl*ND + col]     = v0;
            *(float2*)&Y[(size_t)(rl+8)*ND + col] = v1;
        }
    }
}

// ============================================================
// Kernel 0: permute pad mask into g_maskp
// ============================================================
__global__ __launch_bounds__(256) void mask_perm(const unsigned char* __restrict__ m)
{
    const int i = blockIdx.x*256 + threadIdx.x;          // 0..16383
    const int p = (i & ~7) | ((i & 3) << 1) | ((i >> 2) & 1);
    g_maskp[p] = m[i];
}

// ============================================================
// Kernel 1: projections.  grid=(128, 6). LDT 36, 4 stages (unchanged).
// ============================================================
__global__ __launch_bounds__(256, 1) void proj_mma(
    const float* __restrict__ q_real, const float* __restrict__ q_imag,
    const float* __restrict__ k_real, const float* __restrict__ k_imag,
    const float* __restrict__ v_real, const float* __restrict__ v_imag,
    const float* __restrict__ Wq, const float* __restrict__ bq,
    const float* __restrict__ Wk, const float* __restrict__ bk,
    const float* __restrict__ Wv, const float* __restrict__ bv)
{
    extern __shared__ float smf[];
    const uint32_t sb = smem_u32(smf);
    const int tid = threadIdx.x, lane = tid & 31, wid = tid >> 5;
    const int wm = (wid & 1)*64, wn = (wid >> 1)*64;
    const int m0 = blockIdx.x*128, z = blockIdx.y;
    const float *X, *W, *bias; float* Y;
    switch (z) {
      case 0: X=q_real; W=Wq; bias=bq; Y=g_qr; break;
      case 1: X=q_imag; W=Wq; bias=bq; Y=g_qi; break;
      case 2: X=k_real; W=Wk; bias=bk; Y=g_kr; break;
      case 3: X=k_imag; W=Wk; bias=bk; Y=g_ki; break;
      case 4: X=v_real; W=Wv; bias=bv; Y=g_vrt; break;
      default: X=v_imag; W=Wv; bias=bv; Y=g_vit; break;
    }
    const float* Ab = X + (size_t)m0*ND;
    const int CH = 8;
    float c[4][8][4] = {};
    #pragma unroll
    for (int s = 0; s < 3; s++) {
        cpasyncA<LDT_P>(sb + s*BUF_P*4, Ab + s*32, ND, tid);
        cpasyncB<LDT_P>(sb + (s*BUF_P + ATILE_P)*4, W + s*32, ND, tid);
        CP_COMMIT;
    }
    #pragma unroll 1
    for (int ch = 0; ch < CH; ch++) {
        PIPE_WAIT4(ch, CH);
        __syncthreads();
        if (ch + 3 < CH) {
            const int s = (ch+3) & 3;
            cpasyncA<LDT_P>(sb + s*BUF_P*4, Ab + (ch+3)*32, ND, tid);
            cpasyncB<LDT_P>(sb + (s*BUF_P + ATILE_P)*4, W + (ch+3)*32, ND, tid);
            CP_COMMIT;
        }
        float* base = smf + (ch & 3)*BUF_P;
        mma_block_raw(base, base + ATILE_P, c, wm, wn, lane);
    }
    if (z < 4) {
        epilogueP<true>(c, Y, ND, m0, 0, wm, wn, lane, 1.f, bias);
    } else {
        const int b = m0 >> 12, tok0 = m0 & (NL - 1);
        vt_epilogue(c, smf, bias, Y + (size_t)b*ND*NL, tok0, wm, wn, lane, wid);
    }
}

// ============================================================
// Kernel 2: scores.  grid=(16, 32, 4). LDT 40, 3 stages, distance 2.
// ============================================================
__global__ __launch_bounds__(256, 1) void scores_mma()
{
    extern __shared__ float smf[];
    const uint32_t sb = smem_u32(smf);
    const int tid = threadIdx.x, lane = tid & 31, wid = tid >> 5;
    const int wm = (wid & 1)*64, wn = (wid >> 1)*64;
    const int n0 = blockIdx.x*256, m0 = blockIdx.y*128, b = blockIdx.z;
    const float* APh[2] = { g_qr + (size_t)(b*NL + m0)*ND, g_qi + (size_t)(b*NL + m0)*ND };
    const float* BPh[2] = { g_kr + (size_t)(b*NL + n0)*ND, g_ki + (size_t)(b*NL + n0)*ND };
    const int CH = 16;
    float c[4][8][4] = {};
    #pragma unroll
    for (int s = 0; s < 2; s++) {
        cpasyncA<LDT_G>(sb + s*BUF_G*4, APh[0] + s*32, ND, tid);
        cpasyncB<LDT_G>(sb + (s*BUF_G + ATILE_G)*4, BPh[0] + s*32, ND, tid);
        CP_COMMIT;
    }
    int sc = 0, sp = 2;   // compute stage, prefetch stage (mod 3)
    #pragma unroll 1
    for (int ch = 0; ch < CH; ch++) {
        PIPE_WAIT3(ch, CH);
        __syncthreads();
        if (ch + 2 < CH) {
            const int nc = ch + 2;
            cpasyncA<LDT_G>(sb + sp*BUF_G*4, APh[nc >> 3] + (nc & 7)*32, ND, tid);
            cpasyncB<LDT_G>(sb + (sp*BUF_G + ATILE_G)*4, BPh[nc >> 3] + (nc & 7)*32, ND, tid);
            CP_COMMIT;
        }
        float* base = smf + sc*BUF_G;
        mma_block_perm(base, base + ATILE_G, c, wm, wn, lane);
        sc = (sc + 1 == 3) ? 0 : sc + 1;
        sp = (sp + 1 == 3) ? 0 : sp + 1;
    }
    epilogueP<false>(c, g_s + (size_t)b*NL*NL, NL, m0, n0, wm, wn, lane, SCALE, nullptr);
}

// ============================================================
// Kernel 3: softmax with PERMUTED pad mask; writes probs tf32-rounded
// ============================================================
__global__ __launch_bounds__(256) void softmax_kernel()
{
    __shared__ float sh[8];
    const int row = blockIdx.x, b = row >> 12, t = threadIdx.x;
    float* S = g_s + (size_t)row * NL;
    const unsigned char* m = g_maskp + (size_t)b * NL;
    float v[16];
    #pragma unroll
    for (int j = 0; j < 4; j++) {
        int f4 = t + j*256;
        float4 x = *(const float4*)&S[f4*4];
        uchar4 mk = *(const uchar4*)&m[f4*4];
        v[j*4+0] = mk.x ? -INFINITY : x.x;
        v[j*4+1] = mk.y ? -INFINITY : x.y;
        v[j*4+2] = mk.z ? -INFINITY : x.z;
        v[j*4+3] = mk.w ? -INFINITY : x.w;
    }
    float mx = -INFINITY;
    #pragma unroll
    for (int i = 0; i < 16; i++) mx = fmaxf(mx, v[i]);
    #pragma unroll
    for (int o = 16; o > 0; o >>= 1) mx = fmaxf(mx, __shfl_xor_sync(0xffffffffu, mx, o));
    if ((t & 31) == 0) sh[t >> 5] = mx;
    __syncthreads();
    mx = sh[0];
    #pragma unroll
    for (int i = 1; i < 8; i++) mx = fmaxf(mx, sh[i]);
    __syncthreads();
    float sum = 0.f;
    #pragma unroll
    for (int i = 0; i < 16; i++) { v[i] = __expf(v[i] - mx); sum += v[i]; }
    #pragma unroll
    for (int o = 16; o > 0; o >>= 1) sum += __shfl_xor_sync(0xffffffffu, sum, o);
    if ((t & 31) == 0) sh[t >> 5] = sum;
    __syncthreads();
    sum = 0.f;
    #pragma unroll
    for (int i = 0; i < 8; i++) sum += sh[i];
    const float inv = 1.f / sum;
    #pragma unroll
    for (int j = 0; j < 4; j++) {
        int f4 = t + j*256;
        float4 o;
        o.x = to_tf32(v[j*4+0]*inv); o.y = to_tf32(v[j*4+1]*inv);
        o.z = to_tf32(v[j*4+2]*inv); o.w = to_tf32(v[j*4+3]*inv);
        *(float4*)&S[f4*4] = o;
    }
}

// ============================================================
// Kernel 4: PV + fused LayerNorm.  grid=(2, 32, 4). LDT 40, 3 stages.
// ============================================================
__global__ __launch_bounds__(256, 1) void pv_mma(
    const float* __restrict__ gamma, const float* __restrict__ beta,
    float* __restrict__ out)
{
    extern __shared__ float smf[];
    const uint32_t sb = smem_u32(smf);
    const int tid = threadIdx.x, lane = tid & 31, wid = tid >> 5;
    const int wm = (wid & 1)*64, wn = (wid >> 1)*64;
    const int stream = blockIdx.x, m0 = blockIdx.y*128, b = blockIdx.z;
    const float* Ab = g_s + (size_t)(b*NL + m0)*NL;
    const float* Bb = (stream ? g_vit : g_vrt) + (size_t)b*ND*NL;
    float* Y = out + (size_t)stream*BLD + (size_t)(b*NL + m0)*ND;
    const int CH = 128;
    float c[4][8][4] = {};
    #pragma unroll
    for (int s = 0; s < 2; s++) {
        cpasyncA<LDT_G>(sb + s*BUF_G*4, Ab + s*32, NL, tid);
        cpasyncB<LDT_G>(sb + (s*BUF_G + ATILE_G)*4, Bb + s*32, NL, tid);
        CP_COMMIT;
    }
    int sc = 0, sp = 2;
    #pragma unroll 1
    for (int ch = 0; ch < CH; ch++) {
        PIPE_WAIT3(ch, CH);
        __syncthreads();
        if (ch + 2 < CH) {
            cpasyncA<LDT_G>(sb + sp*BUF_G*4, Ab + (ch+2)*32, NL, tid);
            cpasyncB<LDT_G>(sb + (sp*BUF_G + ATILE_G)*4, Bb + (ch+2)*32, NL, tid);
            CP_COMMIT;
        }
        float* base = smf + sc*BUF_G;
        mma_block_perm(base, base + ATILE_G, c, wm, wn, lane);
        sc = (sc + 1 == 3) ? 0 : sc + 1;
        sp = (sp + 1 == 3) ? 0 : sp + 1;
    }
    ln_epilogue(c, smf, gamma, beta, Y, wm, wn, lane, tid, wid);
}

// ============================================================
extern "C" void kernel_launch(void* const* d_in, const int* in_sizes, int n_in,
                              void* d_out, int out_size)
{
    (void)in_sizes; (void)n_in; (void)out_size;
    const float* q_real = (const float*)d_in[0];
    const float* q_imag = (const float*)d_in[1];
    const float* k_real = (const float*)d_in[2];
    const float* k_imag = (const float*)d_in[3];
    const float* v_real = (const float*)d_in[4];
    const float* v_imag = (const float*)d_in[5];
    const unsigned char* pad_mask = (const unsigned char*)d_in[6];
    const float* Wq = (const float*)d_in[7];
    const float* bq = (const float*)d_in[8];
    const float* Wk = (const float*)d_in[9];
    const float* bk = (const float*)d_in[10];
    const float* Wv = (const float*)d_in[11];
    const float* bv = (const float*)d_in[12];
    const float* gamma = (const float*)d_in[13];
    const float* beta  = (const float*)d_in[14];
    float* out = (float*)d_out;

    cudaFuncSetAttribute(proj_mma,   cudaFuncAttributeMaxDynamicSharedMemorySize, SMEM_P);
    cudaFuncSetAttribute(scores_mma, cudaFuncAttributeMaxDynamicSharedMemorySize, SMEM_G);
    cudaFuncSetAttribute(pv_mma,     cudaFuncAttributeMaxDynamicSharedMemorySize, SMEM_G);

    mask_perm<<<NB*NL/256, 256>>>(pad_mask);
    proj_mma<<<dim3(128, 6), 256, SMEM_P>>>(q_real, q_imag, k_real, k_imag,
                                            v_real, v_imag, Wq, bq, Wk, bk, Wv, bv);
    scores_mma<<<dim3(16, 32, NB), 256, SMEM_G>>>();
    softmax_kernel<<<NB*NL, 256>>>();
    pv_mma<<<dim3(2, 32, NB), 256, SMEM_G>>>(gamma, beta, out);
}

// round 13
// speedup vs baseline: 1.6012x; 1.0979x over previous
#include <cuda_runtime.h>
#include <math.h>
#include <stdint.h>

#define NB 4
#define NL 4096
#define ND 256
#define BLD (NB*NL*ND)
#define SCALE 0.0625f

// ---- scratch (static device globals; allocation is forbidden) ----
__device__ __align__(128) float g_qr[BLD], g_qi[BLD], g_kr[BLD], g_ki[BLD];
__device__ __align__(128) float g_vrt[BLD], g_vit[BLD];    // V transposed [b][d][tok]
__device__ __align__(128) float g_s[(size_t)NB*NL*NL];     // 268MB scores/probs

__device__ __forceinline__ float to_tf32(float x) {
    float y; asm("cvt.rna.tf32.f32 %0, %1;" : "=f"(y) : "f"(x)); return y;
}
__device__ __forceinline__ uint32_t smem_u32(const void* p) {
    uint32_t a;
    asm("{ .reg .u64 t; cvta.to.shared.u64 t, %1; cvt.u32.u64 %0, t; }" : "=r"(a) : "l"(p));
    return a;
}

#define MMA_TF32(c, a, b) \
    asm volatile("mma.sync.aligned.m16n8k8.row.col.f32.tf32.tf32.f32 " \
        "{%0,%1,%2,%3}, {%4,%5,%6,%7}, {%8,%9}, {%0,%1,%2,%3};" \
        : "+f"((c)[0]), "+f"((c)[1]), "+f"((c)[2]), "+f"((c)[3]) \
        : "r"((a)[0]), "r"((a)[1]), "r"((a)[2]), "r"((a)[3]), "r"((b)[0]), "r"((b)[1]))

#define CP_COMMIT asm volatile("cp.async.commit_group;" ::: "memory")
#define CP_WAIT2  asm volatile("cp.async.wait_group 2;" ::: "memory")
#define CP_WAIT1  asm volatile("cp.async.wait_group 1;" ::: "memory")
#define CP_WAIT0  asm volatile("cp.async.wait_group 0;" ::: "memory")

#define LDT 36                    // padded smem row stride (floats)
#define ATILE_F (128*LDT)         // 4608
#define BTILE_F (256*LDT)         // 9216
#define BUF_F (ATILE_F + BTILE_F) // 13824 floats per stage
#define SMEM_BYTES (4*BUF_F*4)    // 221184 B (4 stages)

// pipeline: need chunk ch done; committed groups = min(ch+3, CH)
#define PIPE_WAIT(ch, CH) do { \
    if ((ch) + 3 <= (CH)) CP_WAIT2; \
    else if ((ch) + 2 == (CH)) CP_WAIT1; \
    else CP_WAIT0; } while (0)

// ---- cp.async tile loaders, 256 threads ----
__device__ __forceinline__ void cpasyncA(uint32_t dstbase, const float* __restrict__ p,
                                         size_t ld, int tid) {       // 128x32
    #pragma unroll
    for (int i = 0; i < 4; i++) {
        int pos = tid + i*256, row = pos >> 3, c4 = pos & 7;
        uint32_t dst = dstbase + (uint32_t)(row*LDT + c4*4)*4u;
        asm volatile("cp.async.cg.shared.global [%0], [%1], 16;"
                     :: "r"(dst), "l"(p + (size_t)row*ld + c4*4));
    }
}
__device__ __forceinline__ void cpasyncB(uint32_t dstbase, const float* __restrict__ p,
                                         size_t ld, int tid) {       // 256x32
    #pragma unroll
    for (int i = 0; i < 8; i++) {
        int pos = tid + i*256, row = pos >> 3, c4 = pos & 7;
        uint32_t dst = dstbase + (uint32_t)(row*LDT + c4*4)*4u;
        asm volatile("cp.async.cg.shared.global [%0], [%1], 16;"
                     :: "r"(dst), "l"(p + (size_t)row*ld + c4*4));
    }
}

// ---- fragment loader: one k8 step's operands (16 A + 16 B regs) ----
template<bool CVT>
__device__ __forceinline__ void ld_frag(const float* As, const float* Bs,
                                        uint32_t a[16], uint32_t b[16],
                                        int k0, int wm, int wn, int g, int tg)
{
    #pragma unroll
    for (int i = 0; i < 4; i++) {
        const float* ap = As + (wm + i*16 + g)*LDT + k0 + tg;
        float f0 = ap[0], f1 = ap[8*LDT], f2 = ap[4], f3 = ap[8*LDT + 4];
        if (CVT) { f0 = to_tf32(f0); f1 = to_tf32(f1); f2 = to_tf32(f2); f3 = to_tf32(f3); }
        a[i*4+0] = __float_as_uint(f0);
        a[i*4+1] = __float_as_uint(f1);
        a[i*4+2] = __float_as_uint(f2);
        a[i*4+3] = __float_as_uint(f3);
    }
    #pragma unroll
    for (int j = 0; j < 8; j++) {
        const float* bp = Bs + (wn + j*8 + g)*LDT + k0 + tg;
        float f0 = bp[0], f1 = bp[4];
        if (CVT) { f0 = to_tf32(f0); f1 = to_tf32(f1); }
        b[j*2+0] = __float_as_uint(f0);
        b[j*2+1] = __float_as_uint(f1);
    }
}

// ---- 128x256x32 block step; warp 64x64; register-double-buffered k8 ----
template<bool CVT>
__device__ __forceinline__ void mma_block(const float* As, const float* Bs,
                                          float c[4][8][4], int wm, int wn, int lane)
{
    const int g = lane >> 2, tg = lane & 3;
    uint32_t a[2][16], b[2][16];
    ld_frag<CVT>(As, Bs, a[0], b[0], 0, wm, wn, g, tg);
    #pragma unroll
    for (int k8 = 0; k8 < 4; k8++) {
        const int cur = k8 & 1;
        if (k8 < 3)
            ld_frag<CVT>(As, Bs, a[cur^1], b[cur^1], (k8+1)*8, wm, wn, g, tg);
        #pragma unroll
        for (int j = 0; j < 8; j++)
            #pragma unroll
            for (int i = 0; i < 4; i++)
                MMA_TF32(c[i][j], &a[cur][i*4], &b[cur][j*2]);
    }
}

// generic epilogue (proj Q/K, scores).  ROUND: store tf32-rounded values.
template<bool ROUND>
__device__ __forceinline__ void epilogue(float c[4][8][4], float* __restrict__ out,
                                         size_t ldm, int m0, int n0, int wm, int wn,
                                         int lane, float scale, const float* __restrict__ bias)
{
    const int g = lane >> 2, tg = lane & 3;
    #pragma unroll
    for (int i = 0; i < 4; i++) {
        const int r0 = m0 + wm + i*16 + g;
        #pragma unroll
        for (int j = 0; j < 8; j++) {
            const int col = n0 + wn + j*8 + tg*2;
            float b0 = 0.f, b1 = 0.f;
            if (bias) { b0 = bias[col]; b1 = bias[col+1]; }
            float v00 = c[i][j][0]*scale + b0, v01 = c[i][j][1]*scale + b1;
            float v10 = c[i][j][2]*scale + b0, v11 = c[i][j][3]*scale + b1;
            if (ROUND) { v00 = to_tf32(v00); v01 = to_tf32(v01);
                         v10 = to_tf32(v10); v11 = to_tf32(v11); }
            *(float2*)&out[(size_t)r0*ldm + col]     = make_float2(v00, v01);
            *(float2*)&out[(size_t)(r0+8)*ldm + col] = make_float2(v10, v11);
        }
    }
}

// V epilogue: stage tile in smem, store TRANSPOSED to Yt[d][tok] (tf32-rounded).
// Yt points at this batch's [ND][NL] slab; tok0 is the in-batch token base.
#define VST 257
__device__ __forceinline__ void vt_epilogue(float c[4][8][4], float* stg,
                                            const float* __restrict__ bias,
                                            float* __restrict__ Yt,
                                            int tok0, int wm, int wn, int lane, int wid)
{
    const int g = lane >> 2, tg = lane & 3;
    __syncthreads();                  // mainloop smem free
    #pragma unroll
    for (int i = 0; i < 4; i++) {
        const int r0 = wm + i*16 + g;
        #pragma unroll
        for (int j = 0; j < 8; j++) {
            const int col = wn + j*8 + tg*2;
            const float b0 = bias[col], b1 = bias[col+1];
            stg[r0*VST + col]       = to_tf32(c[i][j][0] + b0);
            stg[r0*VST + col+1]     = to_tf32(c[i][j][1] + b1);
            stg[(r0+8)*VST + col]   = to_tf32(c[i][j][2] + b0);
            stg[(r0+8)*VST + col+1] = to_tf32(c[i][j][3] + b1);
        }
    }
    __syncthreads();
    #pragma unroll
    for (int dd = 0; dd < 32; dd++) {
        const int d = wid*32 + dd;
        float4 v;
        v.x = stg[(lane*4+0)*VST + d];
        v.y = stg[(lane*4+1)*VST + d];
        v.z = stg[(lane*4+2)*VST + d];
        v.w = stg[(lane*4+3)*VST + d];
        *(float4*)&Yt[(size_t)d*NL + tok0 + lane*4] = v;
    }
}

// PV epilogue: cross-warp LayerNorm over 256 cols, then store.
// smem floats: sums [0,512), squares [512,1024), mean [1024,1152),
//              rstd [1152,1280), gamma [1280,1536), beta [1536,1792)
__device__ __forceinline__ void ln_epilogue(float c[4][8][4], float* red,
                                            const float* __restrict__ gamma,
                                            const float* __restrict__ beta,
                                            float* __restrict__ Y,
                                            int wm, int wn, int lane, int tid, int wid)
{
    const int g = lane >> 2, tg = lane & 3;
    const int wg = wid >> 1;          // n-warp group 0..3
    __syncthreads();                  // main loop done; smem free
    red[1280 + tid] = gamma[tid];
    red[1536 + tid] = beta[tid];
    #pragma unroll
    for (int i = 0; i < 4; i++) {
        const int rl = wm + i*16 + g;
        float s0 = 0.f, q0 = 0.f, s1 = 0.f, q1 = 0.f;
        #pragma unroll
        for (int j = 0; j < 8; j++) {
            s0 += c[i][j][0] + c[i][j][1];
            q0 += c[i][j][0]*c[i][j][0] + c[i][j][1]*c[i][j][1];
            s1 += c[i][j][2] + c[i][j][3];
            q1 += c[i][j][2]*c[i][j][2] + c[i][j][3]*c[i][j][3];
        }
        #pragma unroll
        for (int o = 1; o < 4; o <<= 1) {
            s0 += __shfl_xor_sync(0xffffffffu, s0, o);
            q0 += __shfl_xor_sync(0xffffffffu, q0, o);
            s1 += __shfl_xor_sync(0xffffffffu, s1, o);
            q1 += __shfl_xor_sync(0xffffffffu, q1, o);
        }
        if (tg == 0) {
            red[wg*128 + rl]       = s0; red[512 + wg*128 + rl]     = q0;
            red[wg*128 + rl + 8]   = s1; red[512 + wg*128 + rl + 8] = q1;
        }
    }
    __syncthreads();
    if (tid < 128) {
        float s = red[tid] + red[128+tid] + red[256+tid] + red[384+tid];
        float q = red[512+tid] + red[640+tid] + red[768+tid] + red[896+tid];
        float mean = s * (1.f/256.f);
        red[1024 + tid] = mean;
        red[1152 + tid] = rsqrtf(q * (1.f/256.f) - mean*mean + 1e-5f);
    }
    __syncthreads();
    #pragma unroll
    for (int i = 0; i < 4; i++) {
        const int rl = wm + i*16 + g;
        const float m0v = red[1024 + rl],     rs0 = red[1152 + rl];
        const float m1v = red[1024 + rl + 8], rs1 = red[1152 + rl + 8];
        #pragma unroll
        for (int j = 0; j < 8; j++) {
            const int col = wn + j*8 + tg*2;
            const float ga0 = red[1280 + col], ga1 = red[1281 + col];
            const float be0 = red[1536 + col], be1 = red[1537 + col];
            float2 v0 = make_float2((c[i][j][0]-m0v)*rs0*ga0 + be0,
                                    (c[i][j][1]-m0v)*rs0*ga1 + be1);
            float2 v1 = make_float2((c[i][j][2]-m1v)*rs1*ga0 + be0,
                                    (c[i][j][3]-m1v)*rs1*ga1 + be1);
            *(float2*)&Y[(size_t)rl*ND + col]     = v0;
            *(float2*)&Y[(size_t)(rl+8)*ND + col] = v1;
        }
    }
}

// ============================================================
// Kernel 1: projections.  grid=(128, 6). block 128x256, K=256.
// V streams (z=4,5) write TRANSPOSED output directly.
// ============================================================
__global__ __launch_bounds__(256, 1) void proj_mma(
    const float* __restrict__ q_real, const float* __restrict__ q_imag,
    const float* __restrict__ k_real, const float* __restrict__ k_imag,
    const float* __restrict__ v_real, const float* __restrict__ v_imag,
    const float* __restrict__ Wq, const float* __restrict__ bq,
    const float* __restrict__ Wk, const float* __restrict__ bk,
    const float* __restrict__ Wv, const float* __restrict__ bv)
{
    extern __shared__ float smf[];
    const uint32_t sb = smem_u32(smf);
    const int tid = threadIdx.x, lane = tid & 31, wid = tid >> 5;
    const int wm = (wid & 1)*64, wn = (wid >> 1)*64;
    const int m0 = blockIdx.x*128, z = blockIdx.y;
    const float *X, *W, *bias; float* Y;
    switch (z) {
      case 0: X=q_real; W=Wq; bias=bq; Y=g_qr; break;
      case 1: X=q_imag; W=Wq; bias=bq; Y=g_qi; break;
      case 2: X=k_real; W=Wk; bias=bk; Y=g_kr; break;
      case 3: X=k_imag; W=Wk; bias=bk; Y=g_ki; break;
      case 4: X=v_real; W=Wv; bias=bv; Y=g_vrt; break;
      default: X=v_imag; W=Wv; bias=bv; Y=g_vit; break;
    }
    const float* Ab = X + (size_t)m0*ND;
    const int CH = 8;
    float c[4][8][4] = {};
    #pragma unroll
    for (int s = 0; s < 3; s++) {
        cpasyncA(sb + s*BUF_F*4, Ab + s*32, ND, tid);
        cpasyncB(sb + (s*BUF_F + ATILE_F)*4, W + s*32, ND, tid);
        CP_COMMIT;
    }
    #pragma unroll 1
    for (int ch = 0; ch < CH; ch++) {
        PIPE_WAIT(ch, CH);
        __syncthreads();
        if (ch + 3 < CH) {
            const int s = (ch+3) & 3;
            cpasyncA(sb + s*BUF_F*4, Ab + (ch+3)*32, ND, tid);
            cpasyncB(sb + (s*BUF_F + ATILE_F)*4, W + (ch+3)*32, ND, tid);
            CP_COMMIT;
        }
        float* base = smf + (ch & 3)*BUF_F;
        mma_block<true>(base, base + ATILE_F, c, wm, wn, lane);
    }
    if (z < 4) {
        epilogue<true>(c, Y, ND, m0, 0, wm, wn, lane, 1.f, bias);
    } else {
        // decompose global row -> (batch, in-batch token) for [b][d][tok] layout
        const int b = m0 >> 12, tok0 = m0 & (NL - 1);
        vt_epilogue(c, smf, bias, Y + (size_t)b*ND*NL, tok0, wm, wn, lane, wid);
    }
}

// ============================================================
// Kernel 2: scores.  grid=(16, 32, 4). block 128x256, K=512
// ============================================================
__global__ __launch_bounds__(256, 1) void scores_mma()
{
    extern __shared__ float smf[];
    const uint32_t sb = smem_u32(smf);
    const int tid = threadIdx.x, lane = tid & 31, wid = tid >> 5;
    const int wm = (wid & 1)*64, wn = (wid >> 1)*64;
    const int n0 = blockIdx.x*256, m0 = blockIdx.y*128, b = blockIdx.z;
    const float* APh[2] = { g_qr + (size_t)(b*NL + m0)*ND, g_qi + (size_t)(b*NL + m0)*ND };
    const float* BPh[2] = { g_kr + (size_t)(b*NL + n0)*ND, g_ki + (size_t)(b*NL + n0)*ND };
    const int CH = 16;
    float c[4][8][4] = {};
    #pragma unroll
    for (int s = 0; s < 3; s++) {
        cpasyncA(sb + s*BUF_F*4, APh[0] + s*32, ND, tid);
        cpasyncB(sb + (s*BUF_F + ATILE_F)*4, BPh[0] + s*32, ND, tid);
        CP_COMMIT;
    }
    #pragma unroll 1
    for (int ch = 0; ch < CH; ch++) {
        PIPE_WAIT(ch, CH);
        __syncthreads();
        if (ch + 3 < CH) {
            const int nc = ch + 3, s = nc & 3;
            cpasyncA(sb + s*BUF_F*4, APh[nc >> 3] + (nc & 7)*32, ND, tid);
            cpasyncB(sb + (s*BUF_F + ATILE_F)*4, BPh[nc >> 3] + (nc & 7)*32, ND, tid);
            CP_COMMIT;
        }
        float* base = smf + (ch & 3)*BUF_F;
        mma_block<false>(base, base + ATILE_F, c, wm, wn, lane);
    }
    epilogue<false>(c, g_s + (size_t)b*NL*NL, NL, m0, n0, wm, wn, lane, SCALE, nullptr);
}

// ============================================================
// Kernel 3: softmax with pad mask; writes probs tf32-rounded
// ============================================================
__global__ __launch_bounds__(256) void softmax_kernel(const unsigned char* __restrict__ mask)
{
    __shared__ float sh[8];
    const int row = blockIdx.x, b = row >> 12, t = threadIdx.x;
    float* S = g_s + (size_t)row * NL;
    const unsigned char* m = mask + (size_t)b * NL;
    float v[16];
    #pragma unroll
    for (int j = 0; j < 4; j++) {
        int f4 = t + j*256;
        float4 x = *(const float4*)&S[f4*4];
        uchar4 mk = *(const uchar4*)&m[f4*4];
        v[j*4+0] = mk.x ? -INFINITY : x.x;
        v[j*4+1] = mk.y ? -INFINITY : x.y;
        v[j*4+2] = mk.z ? -INFINITY : x.z;
        v[j*4+3] = mk.w ? -INFINITY : x.w;
    }
    float mx = -INFINITY;
    #pragma unroll
    for (int i = 0; i < 16; i++) mx = fmaxf(mx, v[i]);
    #pragma unroll
    for (int o = 16; o > 0; o >>= 1) mx = fmaxf(mx, __shfl_xor_sync(0xffffffffu, mx, o));
    if ((t & 31) == 0) sh[t >> 5] = mx;
    __syncthreads();
    mx = sh[0];
    #pragma unroll
    for (int i = 1; i < 8; i++) mx = fmaxf(mx, sh[i]);
    __syncthreads();
    float sum = 0.f;
    #pragma unroll
    for (int i = 0; i < 16; i++) { v[i] = __expf(v[i] - mx); sum += v[i]; }
    #pragma unroll
    for (int o = 16; o > 0; o >>= 1) sum += __shfl_xor_sync(0xffffffffu, sum, o);
    if ((t & 31) == 0) sh[t >> 5] = sum;
    __syncthreads();
    sum = 0.f;
    #pragma unroll
    for (int i = 0; i < 8; i++) sum += sh[i];
    const float inv = 1.f / sum;
    #pragma unroll
    for (int j = 0; j < 4; j++) {
        int f4 = t + j*256;
        float4 o;
        o.x = to_tf32(v[j*4+0]*inv); o.y = to_tf32(v[j*4+1]*inv);
        o.z = to_tf32(v[j*4+2]*inv); o.w = to_tf32(v[j*4+3]*inv);
        *(float4*)&S[f4*4] = o;
    }
}

// ============================================================
// Kernel 4: PV + fused LayerNorm.  grid=(2 streams, 32, 4). K=4096
// ============================================================
__global__ __launch_bounds__(256, 1) void pv_mma(
    const float* __restrict__ gamma, const float* __restrict__ beta,
    float* __restrict__ out)
{
    extern __shared__ float smf[];
    const uint32_t sb = smem_u32(smf);
    const int tid = threadIdx.x, lane = tid & 31, wid = tid >> 5;
    const int wm = (wid & 1)*64, wn = (wid >> 1)*64;
    const int stream = blockIdx.x, m0 = blockIdx.y*128, b = blockIdx.z;
    const float* Ab = g_s + (size_t)(b*NL + m0)*NL;
    const float* Bb = (stream ? g_vit : g_vrt) + (size_t)b*ND*NL;
    float* Y = out + (size_t)stream*BLD + (size_t)(b*NL + m0)*ND;
    const int CH = 128;
    float c[4][8][4] = {};
    #pragma unroll
    for (int s = 0; s < 3; s++) {
        cpasyncA(sb + s*BUF_F*4, Ab + s*32, NL, tid);
        cpasyncB(sb + (s*BUF_F + ATILE_F)*4, Bb + s*32, NL, tid);
        CP_COMMIT;
    }
    #pragma unroll 1
    for (int ch = 0; ch < CH; ch++) {
        PIPE_WAIT(ch, CH);
        __syncthreads();
        if (ch + 3 < CH) {
            const int s = (ch+3) & 3;
            cpasyncA(sb + s*BUF_F*4, Ab + (ch+3)*32, NL, tid);
            cpasyncB(sb + (s*BUF_F + ATILE_F)*4, Bb + (ch+3)*32, NL, tid);
            CP_COMMIT;
        }
        float* base = smf + (ch & 3)*BUF_F;
        mma_block<false>(base, base + ATILE_F, c, wm, wn, lane);
    }
    ln_epilogue(c, smf, gamma, beta, Y, wm, wn, lane, tid, wid);
}

// ============================================================
extern "C" void kernel_launch(void* const* d_in, const int* in_sizes, int n_in,
                              void* d_out, int out_size)
{
    (void)in_sizes; (void)n_in; (void)out_size;
    const float* q_real = (const float*)d_in[0];
    const float* q_imag = (const float*)d_in[1];
    const float* k_real = (const float*)d_in[2];
    const float* k_imag = (const float*)d_in[3];
    const float* v_real = (const float*)d_in[4];
    const float* v_imag = (const float*)d_in[5];
    const unsigned char* pad_mask = (const unsigned char*)d_in[6];
    const float* Wq = (const float*)d_in[7];
    const float* bq = (const float*)d_in[8];
    const float* Wk = (const float*)d_in[9];
    const float* bk = (const float*)d_in[10];
    const float* Wv = (const float*)d_in[11];
    const float* bv = (const float*)d_in[12];
    const float* gamma = (const float*)d_in[13];
    const float* beta  = (const float*)d_in[14];
    float* out = (float*)d_out;

    cudaFuncSetAttribute(proj_mma,   cudaFuncAttributeMaxDynamicSharedMemorySize, SMEM_BYTES);
    cudaFuncSetAttribute(scores_mma, cudaFuncAttributeMaxDynamicSharedMemorySize, SMEM_BYTES);
    cudaFuncSetAttribute(pv_mma,     cudaFuncAttributeMaxDynamicSharedMemorySize, SMEM_BYTES);

    proj_mma<<<dim3(128, 6), 256, SMEM_BYTES>>>(q_real, q_imag, k_real, k_imag,
                                                v_real, v_imag, Wq, bq, Wk, bk, Wv, bv);
    scores_mma<<<dim3(16, 32, NB), 256, SMEM_BYTES>>>();
    softmax_kernel<<<NB*NL, 256>>>(pad_mask);
    pv_mma<<<dim3(2, 32, NB), 256, SMEM_BYTES>>>(gamma, beta, out);
}

// round 15
// speedup vs baseline: 2.4232x; 1.5134x over previous
#include <cuda_runtime.h>
#include <cuda_fp16.h>
#include <math.h>
#include <stdint.h>

#define NB 4
#define NL 4096
#define ND 256
#define BLD (NB*NL*ND)
#define SCALE 0.0625f

// ---- scratch (static device globals; allocation is forbidden) ----
__device__ __align__(128) __half h_qr[BLD], h_qi[BLD], h_kr[BLD], h_ki[BLD];
__device__ __align__(128) __half h_vrt[BLD], h_vit[BLD];     // V transposed [b][d][tok]
__device__ __align__(128) __half h_s[(size_t)NB*NL*NL];      // 134MB scores/probs

__device__ __forceinline__ float to_tf32(float x) {
    float y; asm("cvt.rna.tf32.f32 %0, %1;" : "=f"(y) : "f"(x)); return y;
}
__device__ __forceinline__ uint32_t smem_u32(const void* p) {
    uint32_t a;
    asm("{ .reg .u64 t; cvta.to.shared.u64 t, %1; cvt.u32.u64 %0, t; }" : "=r"(a) : "l"(p));
    return a;
}
__device__ __forceinline__ uint32_t h2_to_u32(__half2 h) {
    uint32_t u; *(__half2*)&u = h; return u;
}
__device__ __forceinline__ __half2 u32_to_h2(uint32_t u) {
    __half2 h; *(uint32_t*)&h = u; return h;
}

#define MMA_TF32(c, a, b) \
    asm volatile("mma.sync.aligned.m16n8k8.row.col.f32.tf32.tf32.f32 " \
        "{%0,%1,%2,%3}, {%4,%5,%6,%7}, {%8,%9}, {%0,%1,%2,%3};" \
        : "+f"((c)[0]), "+f"((c)[1]), "+f"((c)[2]), "+f"((c)[3]) \
        : "r"((a)[0]), "r"((a)[1]), "r"((a)[2]), "r"((a)[3]), "r"((b)[0]), "r"((b)[1]))

#define MMA_F16(c, a, b) \
    asm volatile("mma.sync.aligned.m16n8k16.row.col.f32.f16.f16.f32 " \
        "{%0,%1,%2,%3}, {%4,%5,%6,%7}, {%8,%9}, {%0,%1,%2,%3};" \
        : "+f"((c)[0]), "+f"((c)[1]), "+f"((c)[2]), "+f"((c)[3]) \
        : "r"((a)[0]), "r"((a)[1]), "r"((a)[2]), "r"((a)[3]), "r"((b)[0]), "r"((b)[1]))

#define CP_COMMIT asm volatile("cp.async.commit_group;" ::: "memory")
#define CP_WAIT2  asm volatile("cp.async.wait_group 2;" ::: "memory")
#define CP_WAIT1  asm volatile("cp.async.wait_group 1;" ::: "memory")
#define CP_WAIT0  asm volatile("cp.async.wait_group 0;" ::: "memory")

// ---- proj (fp32 tf32 path): LDT 36 floats, 4 stages ----
#define LDT 36
#define ATILE_F (128*LDT)
#define BTILE_F (256*LDT)
#define BUF_F (ATILE_F + BTILE_F)
#define SMEM_P (4*BUF_F*4)            // 221184 B

// ---- scores/pv (fp16 path): LDTH 40 halves (20 words), 4 stages ----
#define LDTH 40
#define LDTW 20                       // words per row
#define ATILE_H (128*LDTH)            // 5120 halves
#define BTILE_H (256*LDTH)            // 10240 halves
#define BUF_H (ATILE_H + BTILE_H)     // 15360 halves
#define SMEM_H (4*BUF_H*2)            // 122880 B

#define PIPE_WAIT(ch, CH) do { \
    if ((ch) + 3 <= (CH)) CP_WAIT2; \
    else if ((ch) + 2 == (CH)) CP_WAIT1; \
    else CP_WAIT0; } while (0)

// ---- fp32 cp.async loaders (proj) ----
__device__ __forceinline__ void cpasyncA(uint32_t dstbase, const float* __restrict__ p,
                                         size_t ld, int tid) {
    #pragma unroll
    for (int i = 0; i < 4; i++) {
        int pos = tid + i*256, row = pos >> 3, c4 = pos & 7;
        uint32_t dst = dstbase + (uint32_t)(row*LDT + c4*4)*4u;
        asm volatile("cp.async.cg.shared.global [%0], [%1], 16;"
                     :: "r"(dst), "l"(p + (size_t)row*ld + c4*4));
    }
}
__device__ __forceinline__ void cpasyncB(uint32_t dstbase, const float* __restrict__ p,
                                         size_t ld, int tid) {
    #pragma unroll
    for (int i = 0; i < 8; i++) {
        int pos = tid + i*256, row = pos >> 3, c4 = pos & 7;
        uint32_t dst = dstbase + (uint32_t)(row*LDT + c4*4)*4u;
        asm volatile("cp.async.cg.shared.global [%0], [%1], 16;"
                     :: "r"(dst), "l"(p + (size_t)row*ld + c4*4));
    }
}

// ---- fp16 cp.async loaders (scores/pv): 16B = 8 halves per op ----
__device__ __forceinline__ void cpasyncAH(uint32_t dstbase, const __half* __restrict__ p,
                                          size_t ld, int tid) {       // 128 rows x 32 halves
    #pragma unroll
    for (int i = 0; i < 2; i++) {
        int pos = tid + i*256, row = pos >> 2, c8 = pos & 3;
        uint32_t dst = dstbase + (uint32_t)(row*LDTH + c8*8)*2u;
        asm volatile("cp.async.cg.shared.global [%0], [%1], 16;"
                     :: "r"(dst), "l"(p + (size_t)row*ld + c8*8));
    }
}
__device__ __forceinline__ void cpasyncBH(uint32_t dstbase, const __half* __restrict__ p,
                                          size_t ld, int tid) {       // 256 rows x 32 halves
    #pragma unroll
    for (int i = 0; i < 4; i++) {
        int pos = tid + i*256, row = pos >> 2, c8 = pos & 3;
        uint32_t dst = dstbase + (uint32_t)(row*LDTH + c8*8)*2u;
        asm volatile("cp.async.cg.shared.global [%0], [%1], 16;"
                     :: "r"(dst), "l"(p + (size_t)row*ld + c8*8));
    }
}

// ---- tf32 block step (proj): raw fp32 smem + cvt ----
__device__ __forceinline__ void mma_block_raw(const float* As, const float* Bs,
                                              float c[4][8][4], int wm, int wn, int lane)
{
    const int g = lane >> 2, tg = lane & 3;
    #pragma unroll
    for (int k8 = 0; k8 < 4; k8++) {
        const int k0 = k8*8;
        uint32_t a[4][4];
        #pragma unroll
        for (int i = 0; i < 4; i++) {
            const float* ap = As + (wm + i*16 + g)*LDT + k0 + tg;
            a[i][0] = __float_as_uint(to_tf32(ap[0]));
            a[i][1] = __float_as_uint(to_tf32(ap[8*LDT]));
            a[i][2] = __float_as_uint(to_tf32(ap[4]));
            a[i][3] = __float_as_uint(to_tf32(ap[8*LDT + 4]));
        }
        #pragma unroll
        for (int j = 0; j < 8; j++) {
            const float* bp = Bs + (wn + j*8 + g)*LDT + k0 + tg;
            uint32_t b[2] = { __float_as_uint(to_tf32(bp[0])), __float_as_uint(to_tf32(bp[4])) };
            #pragma unroll
            for (int i = 0; i < 4; i++) MMA_TF32(c[i][j], a[i], b);
        }
    }
}

// ---- fp16 block step (scores/pv): m16n8k16, 2 k-steps per 32-chunk ----
__device__ __forceinline__ void mma_block_h(const uint32_t* Aw, const uint32_t* Bw,
                                            float c[4][8][4], int wm, int wn, int lane)
{
    const int g = lane >> 2, tg = lane & 3;
    #pragma unroll
    for (int s = 0; s < 2; s++) {
        const int ko = s*8;           // k16-step offset in words
        uint32_t a[4][4];
        #pragma unroll
        for (int i = 0; i < 4; i++) {
            const uint32_t* ap = Aw + (wm + i*16 + g)*LDTW + ko + tg;
            a[i][0] = ap[0];
            a[i][1] = ap[8*LDTW];
            a[i][2] = ap[4];
            a[i][3] = ap[8*LDTW + 4];
        }
        #pragma unroll
        for (int j = 0; j < 8; j++) {
            const uint32_t* bp = Bw + (wn + j*8 + g)*LDTW + ko + tg;
            uint32_t b[2] = { bp[0], bp[4] };
            #pragma unroll
            for (int i = 0; i < 4; i++) MMA_F16(c[i][j], a[i], b);
        }
    }
}

// proj Q/K epilogue: fp16 output with bias
__device__ __forceinline__ void epilogueQK(float c[4][8][4], __half* __restrict__ out,
                                           size_t ldm, int m0, int wm, int wn,
                                           int lane, const float* __restrict__ bias)
{
    const int g = lane >> 2, tg = lane & 3;
    #pragma unroll
    for (int i = 0; i < 4; i++) {
        const int r0 = m0 + wm + i*16 + g;
        #pragma unroll
        for (int j = 0; j < 8; j++) {
            const int col = wn + j*8 + tg*2;
            const float b0 = bias[col], b1 = bias[col+1];
            *(__half2*)&out[(size_t)r0*ldm + col] =
                __floats2half2_rn(c[i][j][0] + b0, c[i][j][1] + b1);
            *(__half2*)&out[(size_t)(r0+8)*ldm + col] =
                __floats2half2_rn(c[i][j][2] + b0, c[i][j][3] + b1);
        }
    }
}

// scores epilogue: fp16 output, scaled
__device__ __forceinline__ void epilogueS(float c[4][8][4], __half* __restrict__ out,
                                          size_t ldm, int m0, int n0, int wm, int wn,
                                          int lane, float scale)
{
    const int g = lane >> 2, tg = lane & 3;
    #pragma unroll
    for (int i = 0; i < 4; i++) {
        const int r0 = m0 + wm + i*16 + g;
        #pragma unroll
        for (int j = 0; j < 8; j++) {
            const int col = n0 + wn + j*8 + tg*2;
            *(__half2*)&out[(size_t)r0*ldm + col] =
                __floats2half2_rn(c[i][j][0]*scale, c[i][j][1]*scale);
            *(__half2*)&out[(size_t)(r0+8)*ldm + col] =
                __floats2half2_rn(c[i][j][2]*scale, c[i][j][3]*scale);
        }
    }
}

// V epilogue: stage tile in smem (fp32), store TRANSPOSED fp16 to Yt[d][tok]
#define VST 257
__device__ __forceinline__ void vt_epilogue(float c[4][8][4], float* stg,
                                            const float* __restrict__ bias,
                                            __half* __restrict__ Yt,
                                            int tok0, int wm, int wn, int lane, int wid)
{
    const int g = lane >> 2, tg = lane & 3;
    __syncthreads();                  // mainloop smem free
    #pragma unroll
    for (int i = 0; i < 4; i++) {
        const int r0 = wm + i*16 + g;
        #pragma unroll
        for (int j = 0; j < 8; j++) {
            const int col = wn + j*8 + tg*2;
            const float b0 = bias[col], b1 = bias[col+1];
            stg[r0*VST + col]       = c[i][j][0] + b0;
            stg[r0*VST + col+1]     = c[i][j][1] + b1;
            stg[(r0+8)*VST + col]   = c[i][j][2] + b0;
            stg[(r0+8)*VST + col+1] = c[i][j][3] + b1;
        }
    }
    __syncthreads();
    #pragma unroll
    for (int dd = 0; dd < 32; dd++) {
        const int d = wid*32 + dd;
        uint2 u;
        u.x = h2_to_u32(__floats2half2_rn(stg[(lane*4+0)*VST + d], stg[(lane*4+1)*VST + d]));
        u.y = h2_to_u32(__floats2half2_rn(stg[(lane*4+2)*VST + d], stg[(lane*4+3)*VST + d]));
        *(uint2*)&Yt[(size_t)d*NL + tok0 + lane*4] = u;
    }
}

// PV epilogue: cross-warp LayerNorm over 256 cols, then fp32 store.
__device__ __forceinline__ void ln_epilogue(float c[4][8][4], float* red,
                                            const float* __restrict__ gamma,
                                            const float* __restrict__ beta,
                                            float* __restrict__ Y,
                                            int wm, int wn, int lane, int tid, int wid)
{
    const int g = lane >> 2, tg = lane & 3;
    const int wg = wid >> 1;          // n-warp group 0..3
    __syncthreads();                  // main loop done; smem free
    red[1280 + tid] = gamma[tid];
    red[1536 + tid] = beta[tid];
    #pragma unroll
    for (int i = 0; i < 4; i++) {
        const int rl = wm + i*16 + g;
        float s0 = 0.f, q0 = 0.f, s1 = 0.f, q1 = 0.f;
        #pragma unroll
        for (int j = 0; j < 8; j++) {
            s0 += c[i][j][0] + c[i][j][1];
            q0 += c[i][j][0]*c[i][j][0] + c[i][j][1]*c[i][j][1];
            s1 += c[i][j][2] + c[i][j][3];
            q1 += c[i][j][2]*c[i][j][2] + c[i][j][3]*c[i][j][3];
        }
        #pragma unroll
        for (int o = 1; o < 4; o <<= 1) {
            s0 += __shfl_xor_sync(0xffffffffu, s0, o);
            q0 += __shfl_xor_sync(0xffffffffu, q0, o);
            s1 += __shfl_xor_sync(0xffffffffu, s1, o);
            q1 += __shfl_xor_sync(0xffffffffu, q1, o);
        }
        if (tg == 0) {
            red[wg*128 + rl]       = s0; red[512 + wg*128 + rl]     = q0;
            red[wg*128 + rl + 8]   = s1; red[512 + wg*128 + rl + 8] = q1;
        }
    }
    __syncthreads();
    if (tid < 128) {
        float s = red[tid] + red[128+tid] + red[256+tid] + red[384+tid];
        float q = red[512+tid] + red[640+tid] + red[768+tid] + red[896+tid];
        float mean = s * (1.f/256.f);
        red[1024 + tid] = mean;
        red[1152 + tid] = rsqrtf(q * (1.f/256.f) - mean*mean + 1e-5f);
    }
    __syncthreads();
    #pragma unroll
    for (int i = 0; i < 4; i++) {
        const int rl = wm + i*16 + g;
        const float m0v = red[1024 + rl],     rs0 = red[1152 + rl];
        const float m1v = red[1024 + rl + 8], rs1 = red[1152 + rl + 8];
        #pragma unroll
        for (int j = 0; j < 8; j++) {
            const int col = wn + j*8 + tg*2;
            const float ga0 = red[1280 + col], ga1 = red[1281 + col];
            const float be0 = red[1536 + col], be1 = red[1537 + col];
            float2 v0 = make_float2((c[i][j][0]-m0v)*rs0*ga0 + be0,
                                    (c[i][j][1]-m0v)*rs0*ga1 + be1);
            float2 v1 = make_float2((c[i][j][2]-m1v)*rs1*ga0 + be0,
                                    (c[i][j][3]-m1v)*rs1*ga1 + be1);
            *(float2*)&Y[(size_t)rl*ND + col]     = v0;
            *(float2*)&Y[(size_t)(rl+8)*ND + col] = v1;
        }
    }
}

// ============================================================
// Kernel 1: projections (tf32 mainloop, fp16 outputs).  grid=(128, 6)
// ============================================================
__global__ __launch_bounds__(256, 1) void proj_mma(
    const float* __restrict__ q_real, const float* __restrict__ q_imag,
    const float* __restrict__ k_real, const float* __restrict__ k_imag,
    const float* __restrict__ v_real, const float* __restrict__ v_imag,
    const float* __restrict__ Wq, const float* __restrict__ bq,
    const float* __restrict__ Wk, const float* __restrict__ bk,
    const float* __restrict__ Wv, const float* __restrict__ bv)
{
    extern __shared__ float smf[];
    const uint32_t sb = smem_u32(smf);
    const int tid = threadIdx.x, lane = tid & 31, wid = tid >> 5;
    const int wm = (wid & 1)*64, wn = (wid >> 1)*64;
    const int m0 = blockIdx.x*128, z = blockIdx.y;
    const float *X, *W, *bias; __half* Y;
    switch (z) {
      case 0: X=q_real; W=Wq; bias=bq; Y=h_qr; break;
      case 1: X=q_imag; W=Wq; bias=bq; Y=h_qi; break;
      case 2: X=k_real; W=Wk; bias=bk; Y=h_kr; break;
      case 3: X=k_imag; W=Wk; bias=bk; Y=h_ki; break;
      case 4: X=v_real; W=Wv; bias=bv; Y=h_vrt; break;
      default: X=v_imag; W=Wv; bias=bv; Y=h_vit; break;
    }
    const float* Ab = X + (size_t)m0*ND;
    const int CH = 8;
    float c[4][8][4] = {};
    #pragma unroll
    for (int s = 0; s < 3; s++) {
        cpasyncA(sb + s*BUF_F*4, Ab + s*32, ND, tid);
        cpasyncB(sb + (s*BUF_F + ATILE_F)*4, W + s*32, ND, tid);
        CP_COMMIT;
    }
    #pragma unroll 1
    for (int ch = 0; ch < CH; ch++) {
        PIPE_WAIT(ch, CH);
        __syncthreads();
        if (ch + 3 < CH) {
            const int s = (ch+3) & 3;
            cpasyncA(sb + s*BUF_F*4, Ab + (ch+3)*32, ND, tid);
            cpasyncB(sb + (s*BUF_F + ATILE_F)*4, W + (ch+3)*32, ND, tid);
            CP_COMMIT;
        }
        float* base = smf + (ch & 3)*BUF_F;
        mma_block_raw(base, base + ATILE_F, c, wm, wn, lane);
    }
    if (z < 4) {
        epilogueQK(c, Y, ND, m0, wm, wn, lane, bias);
    } else {
        const int b = m0 >> 12, tok0 = m0 & (NL - 1);
        vt_epilogue(c, smf, bias, Y + (size_t)b*ND*NL, tok0, wm, wn, lane, wid);
    }
}

// ============================================================
// Kernel 2: scores (fp16).  grid=(16, 32, 4). K=512 (16 chunks)
// ============================================================
__global__ __launch_bounds__(256, 1) void scores_mma()
{
    extern __shared__ __half smh[];
    const uint32_t sb = smem_u32(smh);
    const int tid = threadIdx.x, lane = tid & 31, wid = tid >> 5;
    const int wm = (wid & 1)*64, wn = (wid >> 1)*64;
    const int n0 = blockIdx.x*256, m0 = blockIdx.y*128, b = blockIdx.z;
    const __half* APh[2] = { h_qr + (size_t)(b*NL + m0)*ND, h_qi + (size_t)(b*NL + m0)*ND };
    const __half* BPh[2] = { h_kr + (size_t)(b*NL + n0)*ND, h_ki + (size_t)(b*NL + n0)*ND };
    const int CH = 16;
    float c[4][8][4] = {};
    #pragma unroll
    for (int s = 0; s < 3; s++) {
        cpasyncAH(sb + s*BUF_H*2, APh[0] + s*32, ND, tid);
        cpasyncBH(sb + (s*BUF_H + ATILE_H)*2, BPh[0] + s*32, ND, tid);
        CP_COMMIT;
    }
    #pragma unroll 1
    for (int ch = 0; ch < CH; ch++) {
        PIPE_WAIT(ch, CH);
        __syncthreads();
        if (ch + 3 < CH) {
            const int nc = ch + 3, s = nc & 3;
            cpasyncAH(sb + s*BUF_H*2, APh[nc >> 3] + (nc & 7)*32, ND, tid);
            cpasyncBH(sb + (s*BUF_H + ATILE_H)*2, BPh[nc >> 3] + (nc & 7)*32, ND, tid);
            CP_COMMIT;
        }
        const uint32_t* base = (const uint32_t*)(smh + (ch & 3)*BUF_H);
        mma_block_h(base, base + ATILE_H/2, c, wm, wn, lane);
    }
    epilogueS(c, h_s + (size_t)b*NL*NL, NL, m0, n0, wm, wn, lane, SCALE);
}

// ============================================================
// Kernel 3: softmax on fp16 scores; writes fp16 probs
// ============================================================
__global__ __launch_bounds__(256) void softmax_kernel(const unsigned char* __restrict__ mask)
{
    __shared__ float sh[8];
    const int row = blockIdx.x, b = row >> 12, t = threadIdx.x;
    __half* S = h_s + (size_t)row * NL;
    const unsigned char* m = mask + (size_t)b * NL;
    float v[16];
    #pragma unroll
    for (int j = 0; j < 4; j++) {
        int f4 = t + j*256;
        uint2 x = *(const uint2*)&S[f4*4];
        float2 f0 = __half22float2(u32_to_h2(x.x));
        float2 f1 = __half22float2(u32_to_h2(x.y));
        uchar4 mk = *(const uchar4*)&m[f4*4];
        v[j*4+0] = mk.x ? -INFINITY : f0.x;
        v[j*4+1] = mk.y ? -INFINITY : f0.y;
        v[j*4+2] = mk.z ? -INFINITY : f1.x;
        v[j*4+3] = mk.w ? -INFINITY : f1.y;
    }
    float mx = -INFINITY;
    #pragma unroll
    for (int i = 0; i < 16; i++) mx = fmaxf(mx, v[i]);
    #pragma unroll
    for (int o = 16; o > 0; o >>= 1) mx = fmaxf(mx, __shfl_xor_sync(0xffffffffu, mx, o));
    if ((t & 31) == 0) sh[t >> 5] = mx;
    __syncthreads();
    mx = sh[0];
    #pragma unroll
    for (int i = 1; i < 8; i++) mx = fmaxf(mx, sh[i]);
    __syncthreads();
    float sum = 0.f;
    #pragma unroll
    for (int i = 0; i < 16; i++) { v[i] = __expf(v[i] - mx); sum += v[i]; }
    #pragma unroll
    for (int o = 16; o > 0; o >>= 1) sum += __shfl_xor_sync(0xffffffffu, sum, o);
    if ((t & 31) == 0) sh[t >> 5] = sum;
    __syncthreads();
    sum = 0.f;
    #pragma unroll
    for (int i = 0; i < 8; i++) sum += sh[i];
    const float inv = 1.f / sum;
    #pragma unroll
    for (int j = 0; j < 4; j++) {
        int f4 = t + j*256;
        uint2 o;
        o.x = h2_to_u32(__floats2half2_rn(v[j*4+0]*inv, v[j*4+1]*inv));
        o.y = h2_to_u32(__floats2half2_rn(v[j*4+2]*inv, v[j*4+3]*inv));
        *(uint2*)&S[f4*4] = o;
    }
}

// ============================================================
// Kernel 4: PV (fp16) + fused LayerNorm.  grid=(2, 32, 4). K=4096
// ============================================================
__global__ __launch_bounds__(256, 1) void pv_mma(
    const float* __restrict__ gamma, const float* __restrict__ beta,
    float* __restrict__ out)
{
    extern __shared__ __half smh[];
    const uint32_t sb = smem_u32(smh);
    const int tid = threadIdx.x, lane = tid & 31, wid = tid >> 5;
    const int wm = (wid & 1)*64, wn = (wid >> 1)*64;
    const int stream = blockIdx.x, m0 = blockIdx.y*128, b = blockIdx.z;
    const __half* Ab = h_s + (size_t)(b*NL + m0)*NL;
    const __half* Bb = (stream ? h_vit : h_vrt) + (size_t)b*ND*NL;
    float* Y = out + (size_t)stream*BLD + (size_t)(b*NL + m0)*ND;
    const int CH = 128;
    float c[4][8][4] = {};
    #pragma unroll
    for (int s = 0; s < 3; s++) {
        cpasyncAH(sb + s*BUF_H*2, Ab + s*32, NL, tid);
        cpasyncBH(sb + (s*BUF_H + ATILE_H)*2, Bb + s*32, NL, tid);
        CP_COMMIT;
    }
    #pragma unroll 1
    for (int ch = 0; ch < CH; ch++) {
        PIPE_WAIT(ch, CH);
        __syncthreads();
        if (ch + 3 < CH) {
            const int s = (ch+3) & 3;
            cpasyncAH(sb + s*BUF_H*2, Ab + (ch+3)*32, NL, tid);
            cpasyncBH(sb + (s*BUF_H + ATILE_H)*2, Bb + (ch+3)*32, NL, tid);
            CP_COMMIT;
        }
        const uint32_t* base = (const uint32_t*)(smh + (ch & 3)*BUF_H);
        mma_block_h(base, base + ATILE_H/2, c, wm, wn, lane);
    }
    ln_epilogue(c, (float*)smh, gamma, beta, Y, wm, wn, lane, tid, wid);
}

// ============================================================
extern "C" void kernel_launch(void* const* d_in, const int* in_sizes, int n_in,
                              void* d_out, int out_size)
{
    (void)in_sizes; (void)n_in; (void)out_size;
    const float* q_real = (const float*)d_in[0];
    const float* q_imag = (const float*)d_in[1];
    const float* k_real = (const float*)d_in[2];
    const float* k_imag = (const float*)d_in[3];
    const float* v_real = (const float*)d_in[4];
    const float* v_imag = (const float*)d_in[5];
    const unsigned char* pad_mask = (const unsigned char*)d_in[6];
    const float* Wq = (const float*)d_in[7];
    const float* bq = (const float*)d_in[8];
    const float* Wk = (const float*)d_in[9];
    const float* bk = (const float*)d_in[10];
    const float* Wv = (const float*)d_in[11];
    const float* bv = (const float*)d_in[12];
    const float* gamma = (const float*)d_in[13];
    const float* beta  = (const float*)d_in[14];
    float* out = (float*)d_out;

    cudaFuncSetAttribute(proj_mma,   cudaFuncAttributeMaxDynamicSharedMemorySize, SMEM_P);
    cudaFuncSetAttribute(scores_mma, cudaFuncAttributeMaxDynamicSharedMemorySize, SMEM_H);
    cudaFuncSetAttribute(pv_mma,     cudaFuncAttributeMaxDynamicSharedMemorySize, SMEM_H);

    proj_mma<<<dim3(128, 6), 256, SMEM_P>>>(q_real, q_imag, k_real, k_imag,
                                            v_real, v_imag, Wq, bq, Wk, bk, Wv, bv);
    scores_mma<<<dim3(16, 32, NB), 256, SMEM_H>>>();
    softmax_kernel<<<NB*NL, 256>>>(pad_mask);
    pv_mma<<<dim3(2, 32, NB), 256, SMEM_H>>>(gamma, beta, out);
}

// round 16
// speedup vs baseline: 2.7553x; 1.1370x over previous
#include <cuda_runtime.h>
#include <cuda_fp16.h>
#include <math.h>
#include <stdint.h>

#define NB 4
#define NL 4096
#define ND 256
#define BLD (NB*NL*ND)
#define SCALE 0.0625f

// ---- scratch (static device globals; allocation is forbidden) ----
__device__ __align__(128) __half h_qr[BLD], h_qi[BLD], h_kr[BLD], h_ki[BLD];
__device__ __align__(128) __half h_vrt[BLD], h_vit[BLD];     // V transposed [b][d][tok]
__device__ __align__(128) __half h_s[(size_t)NB*NL*NL];      // 134MB scores/probs

__device__ __forceinline__ float to_tf32(float x) {
    float y; asm("cvt.rna.tf32.f32 %0, %1;" : "=f"(y) : "f"(x)); return y;
}
__device__ __forceinline__ uint32_t smem_u32(const void* p) {
    uint32_t a;
    asm("{ .reg .u64 t; cvta.to.shared.u64 t, %1; cvt.u32.u64 %0, t; }" : "=r"(a) : "l"(p));
    return a;
}
__device__ __forceinline__ uint32_t h2_to_u32(__half2 h) {
    uint32_t u; *(__half2*)&u = h; return u;
}
__device__ __forceinline__ __half2 u32_to_h2(uint32_t u) {
    __half2 h; *(uint32_t*)&h = u; return h;
}

#define MMA_TF32(c, a, b) \
    asm volatile("mma.sync.aligned.m16n8k8.row.col.f32.tf32.tf32.f32 " \
        "{%0,%1,%2,%3}, {%4,%5,%6,%7}, {%8,%9}, {%0,%1,%2,%3};" \
        : "+f"((c)[0]), "+f"((c)[1]), "+f"((c)[2]), "+f"((c)[3]) \
        : "r"((a)[0]), "r"((a)[1]), "r"((a)[2]), "r"((a)[3]), "r"((b)[0]), "r"((b)[1]))

#define MMA_F16(c, a, b) \
    asm volatile("mma.sync.aligned.m16n8k16.row.col.f32.f16.f16.f32 " \
        "{%0,%1,%2,%3}, {%4,%5,%6,%7}, {%8,%9}, {%0,%1,%2,%3};" \
        : "+f"((c)[0]), "+f"((c)[1]), "+f"((c)[2]), "+f"((c)[3]) \
        : "r"((a)[0]), "r"((a)[1]), "r"((a)[2]), "r"((a)[3]), "r"((b)[0]), "r"((b)[1]))

#define CP_COMMIT asm volatile("cp.async.commit_group;" ::: "memory")
#define CP_WAIT2  asm volatile("cp.async.wait_group 2;" ::: "memory")
#define CP_WAIT1  asm volatile("cp.async.wait_group 1;" ::: "memory")
#define CP_WAIT0  asm volatile("cp.async.wait_group 0;" ::: "memory")

// ---- proj (fp32 tf32 path): LDT 36 floats, k-chunk 32, 4 stages ----
#define LDT 36
#define ATILE_F (128*LDT)
#define BTILE_F (256*LDT)
#define BUF_F (ATILE_F + BTILE_F)
#define SMEM_P (4*BUF_F*4)            // 221184 B

// ---- scores/pv (fp16 path): k-chunk 64 halves, LDTH 72 (36 words), 4 stages ----
#define LDTH 72
#define LDTW 36                       // words per row (bank residue 4: conflict-free)
#define ATILE_H (128*LDTH)            // 9216 halves
#define BTILE_H (256*LDTH)            // 18432 halves
#define BUF_H (ATILE_H + BTILE_H)     // 27648 halves = 55296 B
#define SMEM_H (4*BUF_H*2)            // 221184 B

#define PIPE_WAIT(ch, CH) do { \
    if ((ch) + 3 <= (CH)) CP_WAIT2; \
    else if ((ch) + 2 == (CH)) CP_WAIT1; \
    else CP_WAIT0; } while (0)

// ---- fp32 cp.async loaders (proj, 32-float chunk) ----
__device__ __forceinline__ void cpasyncA(uint32_t dstbase, const float* __restrict__ p,
                                         size_t ld, int tid) {
    #pragma unroll
    for (int i = 0; i < 4; i++) {
        int pos = tid + i*256, row = pos >> 3, c4 = pos & 7;
        uint32_t dst = dstbase + (uint32_t)(row*LDT + c4*4)*4u;
        asm volatile("cp.async.cg.shared.global [%0], [%1], 16;"
                     :: "r"(dst), "l"(p + (size_t)row*ld + c4*4));
    }
}
__device__ __forceinline__ void cpasyncB(uint32_t dstbase, const float* __restrict__ p,
                                         size_t ld, int tid) {
    #pragma unroll
    for (int i = 0; i < 8; i++) {
        int pos = tid + i*256, row = pos >> 3, c4 = pos & 7;
        uint32_t dst = dstbase + (uint32_t)(row*LDT + c4*4)*4u;
        asm volatile("cp.async.cg.shared.global [%0], [%1], 16;"
                     :: "r"(dst), "l"(p + (size_t)row*ld + c4*4));
    }
}

// ---- fp16 cp.async loaders (64-half chunk: 8 x 16B per row) ----
__device__ __forceinline__ void cpasyncAH(uint32_t dstbase, const __half* __restrict__ p,
                                          size_t ld, int tid) {       // 128 rows x 64 halves
    #pragma unroll
    for (int i = 0; i < 4; i++) {
        int pos = tid + i*256, row = pos >> 3, c8 = pos & 7;
        uint32_t dst = dstbase + (uint32_t)(row*LDTH + c8*8)*2u;
        asm volatile("cp.async.cg.shared.global [%0], [%1], 16;"
                     :: "r"(dst), "l"(p + (size_t)row*ld + c8*8));
    }
}
__device__ __forceinline__ void cpasyncBH(uint32_t dstbase, const __half* __restrict__ p,
                                          size_t ld, int tid) {       // 256 rows x 64 halves
    #pragma unroll
    for (int i = 0; i < 8; i++) {
        int pos = tid + i*256, row = pos >> 3, c8 = pos & 7;
        uint32_t dst = dstbase + (uint32_t)(row*LDTH + c8*8)*2u;
        asm volatile("cp.async.cg.shared.global [%0], [%1], 16;"
                     :: "r"(dst), "l"(p + (size_t)row*ld + c8*8));
    }
}

// ---- tf32 block step (proj): raw fp32 smem + cvt ----
__device__ __forceinline__ void mma_block_raw(const float* As, const float* Bs,
                                              float c[4][8][4], int wm, int wn, int lane)
{
    const int g = lane >> 2, tg = lane & 3;
    #pragma unroll
    for (int k8 = 0; k8 < 4; k8++) {
        const int k0 = k8*8;
        uint32_t a[4][4];
        #pragma unroll
        for (int i = 0; i < 4; i++) {
            const float* ap = As + (wm + i*16 + g)*LDT + k0 + tg;
            a[i][0] = __float_as_uint(to_tf32(ap[0]));
            a[i][1] = __float_as_uint(to_tf32(ap[8*LDT]));
            a[i][2] = __float_as_uint(to_tf32(ap[4]));
            a[i][3] = __float_as_uint(to_tf32(ap[8*LDT + 4]));
        }
        #pragma unroll
        for (int j = 0; j < 8; j++) {
            const float* bp = Bs + (wn + j*8 + g)*LDT + k0 + tg;
            uint32_t b[2] = { __float_as_uint(to_tf32(bp[0])), __float_as_uint(to_tf32(bp[4])) };
            #pragma unroll
            for (int i = 0; i < 4; i++) MMA_TF32(c[i][j], a[i], b);
        }
    }
}

// ---- fp16 block step: 128x256x64 per call; 4 k16-steps ----
__device__ __forceinline__ void mma_block_h(const uint32_t* Aw, const uint32_t* Bw,
                                            float c[4][8][4], int wm, int wn, int lane)
{
    const int g = lane >> 2, tg = lane & 3;
    #pragma unroll
    for (int s = 0; s < 4; s++) {
        const int ko = s*8;           // k16-step offset in words
        uint32_t a[4][4];
        #pragma unroll
        for (int i = 0; i < 4; i++) {
            const uint32_t* ap = Aw + (wm + i*16 + g)*LDTW + ko + tg;
            a[i][0] = ap[0];
            a[i][1] = ap[8*LDTW];
            a[i][2] = ap[4];
            a[i][3] = ap[8*LDTW + 4];
        }
        #pragma unroll
        for (int j = 0; j < 8; j++) {
            const uint32_t* bp = Bw + (wn + j*8 + g)*LDTW + ko + tg;
            uint32_t b[2] = { bp[0], bp[4] };
            #pragma unroll
            for (int i = 0; i < 4; i++) MMA_F16(c[i][j], a[i], b);
        }
    }
}

// proj Q/K epilogue: fp16 output with bias
__device__ __forceinline__ void epilogueQK(float c[4][8][4], __half* __restrict__ out,
                                           size_t ldm, int m0, int wm, int wn,
                                           int lane, const float* __restrict__ bias)
{
    const int g = lane >> 2, tg = lane & 3;
    #pragma unroll
    for (int i = 0; i < 4; i++) {
        const int r0 = m0 + wm + i*16 + g;
        #pragma unroll
        for (int j = 0; j < 8; j++) {
            const int col = wn + j*8 + tg*2;
            const float b0 = bias[col], b1 = bias[col+1];
            *(__half2*)&out[(size_t)r0*ldm + col] =
                __floats2half2_rn(c[i][j][0] + b0, c[i][j][1] + b1);
            *(__half2*)&out[(size_t)(r0+8)*ldm + col] =
                __floats2half2_rn(c[i][j][2] + b0, c[i][j][3] + b1);
        }
    }
}

// scores epilogue: fp16 output, scaled
__device__ __forceinline__ void epilogueS(float c[4][8][4], __half* __restrict__ out,
                                          size_t ldm, int m0, int n0, int wm, int wn,
                                          int lane, float scale)
{
    const int g = lane >> 2, tg = lane & 3;
    #pragma unroll
    for (int i = 0; i < 4; i++) {
        const int r0 = m0 + wm + i*16 + g;
        #pragma unroll
        for (int j = 0; j < 8; j++) {
            const int col = n0 + wn + j*8 + tg*2;
            *(__half2*)&out[(size_t)r0*ldm + col] =
                __floats2half2_rn(c[i][j][0]*scale, c[i][j][1]*scale);
            *(__half2*)&out[(size_t)(r0+8)*ldm + col] =
                __floats2half2_rn(c[i][j][2]*scale, c[i][j][3]*scale);
        }
    }
}

// V epilogue: stage tile in smem (fp32), store TRANSPOSED fp16 to Yt[d][tok]
#define VST 257
__device__ __forceinline__ void vt_epilogue(float c[4][8][4], float* stg,
                                            const float* __restrict__ bias,
                                            __half* __restrict__ Yt,
                                            int tok0, int wm, int wn, int lane, int wid)
{
    const int g = lane >> 2, tg = lane & 3;
    __syncthreads();                  // mainloop smem free
    #pragma unroll
    for (int i = 0; i < 4; i++) {
        const int r0 = wm + i*16 + g;
        #pragma unroll
        for (int j = 0; j < 8; j++) {
            const int col = wn + j*8 + tg*2;
            const float b0 = bias[col], b1 = bias[col+1];
            stg[r0*VST + col]       = c[i][j][0] + b0;
            stg[r0*VST + col+1]     = c[i][j][1] + b1;
            stg[(r0+8)*VST + col]   = c[i][j][2] + b0;
            stg[(r0+8)*VST + col+1] = c[i][j][3] + b1;
        }
    }
    __syncthreads();
    #pragma unroll
    for (int dd = 0; dd < 32; dd++) {
        const int d = wid*32 + dd;
        uint2 u;
        u.x = h2_to_u32(__floats2half2_rn(stg[(lane*4+0)*VST + d], stg[(lane*4+1)*VST + d]));
        u.y = h2_to_u32(__floats2half2_rn(stg[(lane*4+2)*VST + d], stg[(lane*4+3)*VST + d]));
        *(uint2*)&Yt[(size_t)d*NL + tok0 + lane*4] = u;
    }
}

// PV epilogue: cross-warp LayerNorm over 256 cols, then fp32 store.
__device__ __forceinline__ void ln_epilogue(float c[4][8][4], float* red,
                                            const float* __restrict__ gamma,
                                            const float* __restrict__ beta,
                                            float* __restrict__ Y,
                                            int wm, int wn, int lane, int tid, int wid)
{
    const int g = lane >> 2, tg = lane & 3;
    const int wg = wid >> 1;          // n-warp group 0..3
    __syncthreads();                  // main loop done; smem free
    red[1280 + tid] = gamma[tid];
    red[1536 + tid] = beta[tid];
    #pragma unroll
    for (int i = 0; i < 4; i++) {
        const int rl = wm + i*16 + g;
        float s0 = 0.f, q0 = 0.f, s1 = 0.f, q1 = 0.f;
        #pragma unroll
        for (int j = 0; j < 8; j++) {
            s0 += c[i][j][0] + c[i][j][1];
            q0 += c[i][j][0]*c[i][j][0] + c[i][j][1]*c[i][j][1];
            s1 += c[i][j][2] + c[i][j][3];
            q1 += c[i][j][2]*c[i][j][2] + c[i][j][3]*c[i][j][3];
        }
        #pragma unroll
        for (int o = 1; o < 4; o <<= 1) {
            s0 += __shfl_xor_sync(0xffffffffu, s0, o);
            q0 += __shfl_xor_sync(0xffffffffu, q0, o);
            s1 += __shfl_xor_sync(0xffffffffu, s1, o);
            q1 += __shfl_xor_sync(0xffffffffu, q1, o);
        }
        if (tg == 0) {
            red[wg*128 + rl]       = s0; red[512 + wg*128 + rl]     = q0;
            red[wg*128 + rl + 8]   = s1; red[512 + wg*128 + rl + 8] = q1;
        }
    }
    __syncthreads();
    if (tid < 128) {
        float s = red[tid] + red[128+tid] + red[256+tid] + red[384+tid];
        float q = red[512+tid] + red[640+tid] + red[768+tid] + red[896+tid];
        float mean = s * (1.f/256.f);
        red[1024 + tid] = mean;
        red[1152 + tid] = rsqrtf(q * (1.f/256.f) - mean*mean + 1e-5f);
    }
    __syncthreads();
    #pragma unroll
    for (int i = 0; i < 4; i++) {
        const int rl = wm + i*16 + g;
        const float m0v = red[1024 + rl],     rs0 = red[1152 + rl];
        const float m1v = red[1024 + rl + 8], rs1 = red[1152 + rl + 8];
        #pragma unroll
        for (int j = 0; j < 8; j++) {
            const int col = wn + j*8 + tg*2;
            const float ga0 = red[1280 + col], ga1 = red[1281 + col];
            const float be0 = red[1536 + col], be1 = red[1537 + col];
            float2 v0 = make_float2((c[i][j][0]-m0v)*rs0*ga0 + be0,
                                    (c[i][j][1]-m0v)*rs0*ga1 + be1);
            float2 v1 = make_float2((c[i][j][2]-m1v)*rs1*ga0 + be0,
                                    (c[i][j][3]-m1v)*rs1*ga1 + be1);
            *(float2*)&Y[(size_t)rl*ND + col]     = v0;
            *(float2*)&Y[(size_t)(rl+8)*ND + col] = v1;
        }
    }
}

// ============================================================
// Kernel 1: projections (tf32 mainloop, fp16 outputs).  grid=(128, 6)
// ============================================================
__global__ __launch_bounds__(256, 1) void proj_mma(
    const float* __restrict__ q_real, const float* __restrict__ q_imag,
    const float* __restrict__ k_real, const float* __restrict__ k_imag,
    const float* __restrict__ v_real, const float* __restrict__ v_imag,
    const float* __restrict__ Wq, const float* __restrict__ bq,
    const float* __restrict__ Wk, const float* __restrict__ bk,
    const float* __restrict__ Wv, const float* __restrict__ bv)
{
    extern __shared__ float smf[];
    const uint32_t sb = smem_u32(smf);
    const int tid = threadIdx.x, lane = tid & 31, wid = tid >> 5;
    const int wm = (wid & 1)*64, wn = (wid >> 1)*64;
    const int m0 = blockIdx.x*128, z = blockIdx.y;
    const float *X, *W, *bias; __half* Y;
    switch (z) {
      case 0: X=q_real; W=Wq; bias=bq; Y=h_qr; break;
      case 1: X=q_imag; W=Wq; bias=bq; Y=h_qi; break;
      case 2: X=k_real; W=Wk; bias=bk; Y=h_kr; break;
      case 3: X=k_imag; W=Wk; bias=bk; Y=h_ki; break;
      case 4: X=v_real; W=Wv; bias=bv; Y=h_vrt; break;
      default: X=v_imag; W=Wv; bias=bv; Y=h_vit; break;
    }
    const float* Ab = X + (size_t)m0*ND;
    const int CH = 8;
    float c[4][8][4] = {};
    #pragma unroll
    for (int s = 0; s < 3; s++) {
        cpasyncA(sb + s*BUF_F*4, Ab + s*32, ND, tid);
        cpasyncB(sb + (s*BUF_F + ATILE_F)*4, W + s*32, ND, tid);
        CP_COMMIT;
    }
    #pragma unroll 1
    for (int ch = 0; ch < CH; ch++) {
        PIPE_WAIT(ch, CH);
        __syncthreads();
        if (ch + 3 < CH) {
            const int s = (ch+3) & 3;
            cpasyncA(sb + s*BUF_F*4, Ab + (ch+3)*32, ND, tid);
            cpasyncB(sb + (s*BUF_F + ATILE_F)*4, W + (ch+3)*32, ND, tid);
            CP_COMMIT;
        }
        float* base = smf + (ch & 3)*BUF_F;
        mma_block_raw(base, base + ATILE_F, c, wm, wn, lane);
    }
    if (z < 4) {
        epilogueQK(c, Y, ND, m0, wm, wn, lane, bias);
    } else {
        const int b = m0 >> 12, tok0 = m0 & (NL - 1);
        vt_epilogue(c, smf, bias, Y + (size_t)b*ND*NL, tok0, wm, wn, lane, wid);
    }
}

// ============================================================
// Kernel 2: scores (fp16).  grid=(16, 32, 4). K=512 (8 chunks of 64)
// ============================================================
__global__ __launch_bounds__(256, 1) void scores_mma()
{
    extern __shared__ __half smh[];
    const uint32_t sb = smem_u32(smh);
    const int tid = threadIdx.x, lane = tid & 31, wid = tid >> 5;
    const int wm = (wid & 1)*64, wn = (wid >> 1)*64;
    const int n0 = blockIdx.x*256, m0 = blockIdx.y*128, b = blockIdx.z;
    const __half* APh[2] = { h_qr + (size_t)(b*NL + m0)*ND, h_qi + (size_t)(b*NL + m0)*ND };
    const __half* BPh[2] = { h_kr + (size_t)(b*NL + n0)*ND, h_ki + (size_t)(b*NL + n0)*ND };
    const int CH = 8;                 // phase = ch>>2, k0 = (ch&3)*64
    float c[4][8][4] = {};
    #pragma unroll
    for (int s = 0; s < 3; s++) {
        cpasyncAH(sb + s*BUF_H*2, APh[0] + s*64, ND, tid);
        cpasyncBH(sb + (s*BUF_H + ATILE_H)*2, BPh[0] + s*64, ND, tid);
        CP_COMMIT;
    }
    #pragma unroll 1
    for (int ch = 0; ch < CH; ch++) {
        PIPE_WAIT(ch, CH);
        __syncthreads();
        if (ch + 3 < CH) {
            const int nc = ch + 3, s = nc & 3;
            cpasyncAH(sb + s*BUF_H*2, APh[nc >> 2] + (nc & 3)*64, ND, tid);
            cpasyncBH(sb + (s*BUF_H + ATILE_H)*2, BPh[nc >> 2] + (nc & 3)*64, ND, tid);
            CP_COMMIT;
        }
        const uint32_t* base = (const uint32_t*)(smh + (ch & 3)*BUF_H);
        mma_block_h(base, base + ATILE_H/2, c, wm, wn, lane);
    }
    epilogueS(c, h_s + (size_t)b*NL*NL, NL, m0, n0, wm, wn, lane, SCALE);
}

// ============================================================
// Kernel 3: softmax on fp16 scores; writes fp16 probs
// ============================================================
__global__ __launch_bounds__(256) void softmax_kernel(const unsigned char* __restrict__ mask)
{
    __shared__ float sh[8];
    const int row = blockIdx.x, b = row >> 12, t = threadIdx.x;
    __half* S = h_s + (size_t)row * NL;
    const unsigned char* m = mask + (size_t)b * NL;
    float v[16];
    #pragma unroll
    for (int j = 0; j < 4; j++) {
        int f4 = t + j*256;
        uint2 x = *(const uint2*)&S[f4*4];
        float2 f0 = __half22float2(u32_to_h2(x.x));
        float2 f1 = __half22float2(u32_to_h2(x.y));
        uchar4 mk = *(const uchar4*)&m[f4*4];
        v[j*4+0] = mk.x ? -INFINITY : f0.x;
        v[j*4+1] = mk.y ? -INFINITY : f0.y;
        v[j*4+2] = mk.z ? -INFINITY : f1.x;
        v[j*4+3] = mk.w ? -INFINITY : f1.y;
    }
    float mx = -INFINITY;
    #pragma unroll
    for (int i = 0; i < 16; i++) mx = fmaxf(mx, v[i]);
    #pragma unroll
    for (int o = 16; o > 0; o >>= 1) mx = fmaxf(mx, __shfl_xor_sync(0xffffffffu, mx, o));
    if ((t & 31) == 0) sh[t >> 5] = mx;
    __syncthreads();
    mx = sh[0];
    #pragma unroll
    for (int i = 1; i < 8; i++) mx = fmaxf(mx, sh[i]);
    __syncthreads();
    float sum = 0.f;
    #pragma unroll
    for (int i = 0; i < 16; i++) { v[i] = __expf(v[i] - mx); sum += v[i]; }
    #pragma unroll
    for (int o = 16; o > 0; o >>= 1) sum += __shfl_xor_sync(0xffffffffu, sum, o);
    if ((t & 31) == 0) sh[t >> 5] = sum;
    __syncthreads();
    sum = 0.f;
    #pragma unroll
    for (int i = 0; i < 8; i++) sum += sh[i];
    const float inv = 1.f / sum;
    #pragma unroll
    for (int j = 0; j < 4; j++) {
        int f4 = t + j*256;
        uint2 o;
        o.x = h2_to_u32(__floats2half2_rn(v[j*4+0]*inv, v[j*4+1]*inv));
        o.y = h2_to_u32(__floats2half2_rn(v[j*4+2]*inv, v[j*4+3]*inv));
        *(uint2*)&S[f4*4] = o;
    }
}

// ============================================================
// Kernel 4: PV (fp16) + fused LayerNorm.  grid=(2, 32, 4). K=4096 (64 chunks)
// ============================================================
__global__ __launch_bounds__(256, 1) void pv_mma(
    const float* __restrict__ gamma, const float* __restrict__ beta,
    float* __restrict__ out)
{
    extern __shared__ __half smh[];
    const uint32_t sb = smem_u32(smh);
    const int tid = threadIdx.x, lane = tid & 31, wid = tid >> 5;
    const int wm = (wid & 1)*64, wn = (wid >> 1)*64;
    const int stream = blockIdx.x, m0 = blockIdx.y*128, b = blockIdx.z;
    const __half* Ab = h_s + (size_t)(b*NL + m0)*NL;
    const __half* Bb = (stream ? h_vit : h_vrt) + (size_t)b*ND*NL;
    float* Y = out + (size_t)stream*BLD + (size_t)(b*NL + m0)*ND;
    const int CH = 64;
    float c[4][8][4] = {};
    #pragma unroll
    for (int s = 0; s < 3; s++) {
        cpasyncAH(sb + s*BUF_H*2, Ab + s*64, NL, tid);
        cpasyncBH(sb + (s*BUF_H + ATILE_H)*2, Bb + s*64, NL, tid);
        CP_COMMIT;
    }
    #pragma unroll 1
    for (int ch = 0; ch < CH; ch++) {
        PIPE_WAIT(ch, CH);
        __syncthreads();
        if (ch + 3 < CH) {
            const int s = (ch+3) & 3;
            cpasyncAH(sb + s*BUF_H*2, Ab + (ch+3)*64, NL, tid);
            cpasyncBH(sb + (s*BUF_H + ATILE_H)*2, Bb + (ch+3)*64, NL, tid);
            CP_COMMIT;
        }
        const uint32_t* base = (const uint32_t*)(smh + (ch & 3)*BUF_H);
        mma_block_h(base, base + ATILE_H/2, c, wm, wn, lane);
    }
    ln_epilogue(c, (float*)smh, gamma, beta, Y, wm, wn, lane, tid, wid);
}

// ============================================================
extern "C" void kernel_launch(void* const* d_in, const int* in_sizes, int n_in,
                              void* d_out, int out_size)
{
    (void)in_sizes; (void)n_in; (void)out_size;
    const float* q_real = (const float*)d_in[0];
    const float* q_imag = (const float*)d_in[1];
    const float* k_real = (const float*)d_in[2];
    const float* k_imag = (const float*)d_in[3];
    const float* v_real = (const float*)d_in[4];
    const float* v_imag = (const float*)d_in[5];
    const unsigned char* pad_mask = (const unsigned char*)d_in[6];
    const float* Wq = (const float*)d_in[7];
    const float* bq = (const float*)d_in[8];
    const float* Wk = (const float*)d_in[9];
    const float* bk = (const float*)d_in[10];
    const float* Wv = (const float*)d_in[11];
    const float* bv = (const float*)d_in[12];
    const float* gamma = (const float*)d_in[13];
    const float* beta  = (const float*)d_in[14];
    float* out = (float*)d_out;

    cudaFuncSetAttribute(proj_mma,   cudaFuncAttributeMaxDynamicSharedMemorySize, SMEM_P);
    cudaFuncSetAttribute(scores_mma, cudaFuncAttributeMaxDynamicSharedMemorySize, SMEM_H);
    cudaFuncSetAttribute(pv_mma,     cudaFuncAttributeMaxDynamicSharedMemorySize, SMEM_H);

    proj_mma<<<dim3(128, 6), 256, SMEM_P>>>(q_real, q_imag, k_real, k_imag,
                                            v_real, v_imag, Wq, bq, Wk, bk, Wv, bv);
    scores_mma<<<dim3(16, 32, NB), 256, SMEM_H>>>();
    softmax_kernel<<<NB*NL, 256>>>(pad_mask);
    pv_mma<<<dim3(2, 32, NB), 256, SMEM_H>>>(gamma, beta, out);
}

// round 17
// speedup vs baseline: 2.7576x; 1.0008x over previous
#include <cuda_runtime.h>
#include <cuda_fp16.h>
#include <math.h>
#include <stdint.h>

#define NB 4
#define NL 4096
#define ND 256
#define BLD (NB*NL*ND)
#define SCALE 0.0625f

// ---- scratch (static device globals; allocation is forbidden) ----
__device__ __align__(128) __half h_qr[BLD], h_qi[BLD], h_kr[BLD], h_ki[BLD];
__device__ __align__(128) __half h_vrt[BLD], h_vit[BLD];     // V transposed [b][d][tok]
__device__ __align__(128) __half h_s[(size_t)NB*NL*NL];      // 134MB scores/probs

__device__ __forceinline__ float to_tf32(float x) {
    float y; asm("cvt.rna.tf32.f32 %0, %1;" : "=f"(y) : "f"(x)); return y;
}
__device__ __forceinline__ uint32_t smem_u32(const void* p) {
    uint32_t a;
    asm("{ .reg .u64 t; cvta.to.shared.u64 t, %1; cvt.u32.u64 %0, t; }" : "=r"(a) : "l"(p));
    return a;
}
__device__ __forceinline__ uint32_t h2_to_u32(__half2 h) {
    uint32_t u; *(__half2*)&u = h; return u;
}
__device__ __forceinline__ __half2 u32_to_h2(uint32_t u) {
    __half2 h; *(uint32_t*)&h = u; return h;
}

#define MMA_TF32(c, a, b) \
    asm volatile("mma.sync.aligned.m16n8k8.row.col.f32.tf32.tf32.f32 " \
        "{%0,%1,%2,%3}, {%4,%5,%6,%7}, {%8,%9}, {%0,%1,%2,%3};" \
        : "+f"((c)[0]), "+f"((c)[1]), "+f"((c)[2]), "+f"((c)[3]) \
        : "r"((a)[0]), "r"((a)[1]), "r"((a)[2]), "r"((a)[3]), "r"((b)[0]), "r"((b)[1]))

#define MMA_F16(c, a, b) \
    asm volatile("mma.sync.aligned.m16n8k16.row.col.f32.f16.f16.f32 " \
        "{%0,%1,%2,%3}, {%4,%5,%6,%7}, {%8,%9}, {%0,%1,%2,%3};" \
        : "+f"((c)[0]), "+f"((c)[1]), "+f"((c)[2]), "+f"((c)[3]) \
        : "r"((a)[0]), "r"((a)[1]), "r"((a)[2]), "r"((a)[3]), "r"((b)[0]), "r"((b)[1]))

// fp16 accumulator variant (full-rate)
#define MMA_F16A(c, a, b) \
    asm volatile("mma.sync.aligned.m16n8k16.row.col.f16.f16.f16.f16 " \
        "{%0,%1}, {%2,%3,%4,%5}, {%6,%7}, {%0,%1};" \
        : "+r"((c)[0]), "+r"((c)[1]) \
        : "r"((a)[0]), "r"((a)[1]), "r"((a)[2]), "r"((a)[3]), "r"((b)[0]), "r"((b)[1]))

#define CP_COMMIT asm volatile("cp.async.commit_group;" ::: "memory")
#define CP_WAIT2  asm volatile("cp.async.wait_group 2;" ::: "memory")
#define CP_WAIT1  asm volatile("cp.async.wait_group 1;" ::: "memory")
#define CP_WAIT0  asm volatile("cp.async.wait_group 0;" ::: "memory")

// ---- proj (fp32 tf32 path): LDT 36 floats, k-chunk 32, 4 stages ----
#define LDT 36
#define ATILE_F (128*LDT)
#define BTILE_F (256*LDT)
#define BUF_F (ATILE_F + BTILE_F)
#define SMEM_P (4*BUF_F*4)            // 221184 B

// ---- scores/pv (fp16 path): k-chunk 64 halves, LDTH 72 (36 words), 4 stages ----
#define LDTH 72
#define LDTW 36
#define ATILE_H (128*LDTH)
#define BTILE_H (256*LDTH)
#define BUF_H (ATILE_H + BTILE_H)     // 27648 halves = 55296 B
#define SMEM_H (4*BUF_H*2)            // 221184 B

#define PIPE_WAIT(ch, CH) do { \
    if ((ch) + 3 <= (CH)) CP_WAIT2; \
    else if ((ch) + 2 == (CH)) CP_WAIT1; \
    else CP_WAIT0; } while (0)

// ---- fp32 cp.async loaders (proj) ----
__device__ __forceinline__ void cpasyncA(uint32_t dstbase, const float* __restrict__ p,
                                         size_t ld, int tid) {
    #pragma unroll
    for (int i = 0; i < 4; i++) {
        int pos = tid + i*256, row = pos >> 3, c4 = pos & 7;
        uint32_t dst = dstbase + (uint32_t)(row*LDT + c4*4)*4u;
        asm volatile("cp.async.cg.shared.global [%0], [%1], 16;"
                     :: "r"(dst), "l"(p + (size_t)row*ld + c4*4));
    }
}
__device__ __forceinline__ void cpasyncB(uint32_t dstbase, const float* __restrict__ p,
                                         size_t ld, int tid) {
    #pragma unroll
    for (int i = 0; i < 8; i++) {
        int pos = tid + i*256, row = pos >> 3, c4 = pos & 7;
        uint32_t dst = dstbase + (uint32_t)(row*LDT + c4*4)*4u;
        asm volatile("cp.async.cg.shared.global [%0], [%1], 16;"
                     :: "r"(dst), "l"(p + (size_t)row*ld + c4*4));
    }
}

// ---- fp16 cp.async loaders (64-half chunk) ----
__device__ __forceinline__ void cpasyncAH(uint32_t dstbase, const __half* __restrict__ p,
                                          size_t ld, int tid) {       // 128 rows x 64 halves
    #pragma unroll
    for (int i = 0; i < 4; i++) {
        int pos = tid + i*256, row = pos >> 3, c8 = pos & 7;
        uint32_t dst = dstbase + (uint32_t)(row*LDTH + c8*8)*2u;
        asm volatile("cp.async.cg.shared.global [%0], [%1], 16;"
                     :: "r"(dst), "l"(p + (size_t)row*ld + c8*8));
    }
}
__device__ __forceinline__ void cpasyncBH(uint32_t dstbase, const __half* __restrict__ p,
                                          size_t ld, int tid) {       // 256 rows x 64 halves
    #pragma unroll
    for (int i = 0; i < 8; i++) {
        int pos = tid + i*256, row = pos >> 3, c8 = pos & 7;
        uint32_t dst = dstbase + (uint32_t)(row*LDTH + c8*8)*2u;
        asm volatile("cp.async.cg.shared.global [%0], [%1], 16;"
                     :: "r"(dst), "l"(p + (size_t)row*ld + c8*8));
    }
}

// ---- tf32 block step (proj) ----
__device__ __forceinline__ void mma_block_raw(const float* As, const float* Bs,
                                              float c[4][8][4], int wm, int wn, int lane)
{
    const int g = lane >> 2, tg = lane & 3;
    #pragma unroll
    for (int k8 = 0; k8 < 4; k8++) {
        const int k0 = k8*8;
        uint32_t a[4][4];
        #pragma unroll
        for (int i = 0; i < 4; i++) {
            const float* ap = As + (wm + i*16 + g)*LDT + k0 + tg;
            a[i][0] = __float_as_uint(to_tf32(ap[0]));
            a[i][1] = __float_as_uint(to_tf32(ap[8*LDT]));
            a[i][2] = __float_as_uint(to_tf32(ap[4]));
            a[i][3] = __float_as_uint(to_tf32(ap[8*LDT + 4]));
        }
        #pragma unroll
        for (int j = 0; j < 8; j++) {
            const float* bp = Bs + (wn + j*8 + g)*LDT + k0 + tg;
            uint32_t b[2] = { __float_as_uint(to_tf32(bp[0])), __float_as_uint(to_tf32(bp[4])) };
            #pragma unroll
            for (int i = 0; i < 4; i++) MMA_TF32(c[i][j], a[i], b);
        }
    }
}

// ---- fp16 block step, f32 accum (pv): 128x256x64; 4 k16-steps ----
__device__ __forceinline__ void mma_block_h(const uint32_t* Aw, const uint32_t* Bw,
                                            float c[4][8][4], int wm, int wn, int lane)
{
    const int g = lane >> 2, tg = lane & 3;
    #pragma unroll
    for (int s = 0; s < 4; s++) {
        const int ko = s*8;
        uint32_t a[4][4];
        #pragma unroll
        for (int i = 0; i < 4; i++) {
            const uint32_t* ap = Aw + (wm + i*16 + g)*LDTW + ko + tg;
            a[i][0] = ap[0];
            a[i][1] = ap[8*LDTW];
            a[i][2] = ap[4];
            a[i][3] = ap[8*LDTW + 4];
        }
        #pragma unroll
        for (int j = 0; j < 8; j++) {
            const uint32_t* bp = Bw + (wn + j*8 + g)*LDTW + ko + tg;
            uint32_t b[2] = { bp[0], bp[4] };
            #pragma unroll
            for (int i = 0; i < 4; i++) MMA_F16(c[i][j], a[i], b);
        }
    }
}

// ---- fp16 block step, f16 accum (scores): full-rate ----
__device__ __forceinline__ void mma_block_h16(const uint32_t* Aw, const uint32_t* Bw,
                                              uint32_t c[4][8][2], int wm, int wn, int lane)
{
    const int g = lane >> 2, tg = lane & 3;
    #pragma unroll
    for (int s = 0; s < 4; s++) {
        const int ko = s*8;
        uint32_t a[4][4];
        #pragma unroll
        for (int i = 0; i < 4; i++) {
            const uint32_t* ap = Aw + (wm + i*16 + g)*LDTW + ko + tg;
            a[i][0] = ap[0];
            a[i][1] = ap[8*LDTW];
            a[i][2] = ap[4];
            a[i][3] = ap[8*LDTW + 4];
        }
        #pragma unroll
        for (int j = 0; j < 8; j++) {
            const uint32_t* bp = Bw + (wn + j*8 + g)*LDTW + ko + tg;
            uint32_t b[2] = { bp[0], bp[4] };
            #pragma unroll
            for (int i = 0; i < 4; i++) MMA_F16A(c[i][j], a[i], b);
        }
    }
}

// proj Q/K epilogue: fp16 output with bias
__device__ __forceinline__ void epilogueQK(float c[4][8][4], __half* __restrict__ out,
                                           size_t ldm, int m0, int wm, int wn,
                                           int lane, const float* __restrict__ bias)
{
    const int g = lane >> 2, tg = lane & 3;
    #pragma unroll
    for (int i = 0; i < 4; i++) {
        const int r0 = m0 + wm + i*16 + g;
        #pragma unroll
        for (int j = 0; j < 8; j++) {
            const int col = wn + j*8 + tg*2;
            const float b0 = bias[col], b1 = bias[col+1];
            *(__half2*)&out[(size_t)r0*ldm + col] =
                __floats2half2_rn(c[i][j][0] + b0, c[i][j][1] + b1);
            *(__half2*)&out[(size_t)(r0+8)*ldm + col] =
                __floats2half2_rn(c[i][j][2] + b0, c[i][j][3] + b1);
        }
    }
}

// scores epilogue from f16 accumulators: scale in half2, store
__device__ __forceinline__ void epilogueS16(uint32_t c[4][8][2], __half* __restrict__ out,
                                            size_t ldm, int m0, int n0, int wm, int wn,
                                            int lane)
{
    const int g = lane >> 2, tg = lane & 3;
    const __half2 sc = __float2half2_rn(SCALE);
    #pragma unroll
    for (int i = 0; i < 4; i++) {
        const int r0 = m0 + wm + i*16 + g;
        #pragma unroll
        for (int j = 0; j < 8; j++) {
            const int col = n0 + wn + j*8 + tg*2;
            *(__half2*)&out[(size_t)r0*ldm + col]     = __hmul2(u32_to_h2(c[i][j][0]), sc);
            *(__half2*)&out[(size_t)(r0+8)*ldm + col] = __hmul2(u32_to_h2(c[i][j][1]), sc);
        }
    }
}

// V epilogue: stage tile in smem (fp32), store TRANSPOSED fp16 to Yt[d][tok]
#define VST 257
__device__ __forceinline__ void vt_epilogue(float c[4][8][4], float* stg,
                                            const float* __restrict__ bias,
                                            __half* __restrict__ Yt,
                                            int tok0, int wm, int wn, int lane, int wid)
{
    const int g = lane >> 2, tg = lane & 3;
    __syncthreads();
    #pragma unroll
    for (int i = 0; i < 4; i++) {
        const int r0 = wm + i*16 + g;
        #pragma unroll
        for (int j = 0; j < 8; j++) {
            const int col = wn + j*8 + tg*2;
            const float b0 = bias[col], b1 = bias[col+1];
            stg[r0*VST + col]       = c[i][j][0] + b0;
            stg[r0*VST + col+1]     = c[i][j][1] + b1;
            stg[(r0+8)*VST + col]   = c[i][j][2] + b0;
            stg[(r0+8)*VST + col+1] = c[i][j][3] + b1;
        }
    }
    __syncthreads();
    #pragma unroll
    for (int dd = 0; dd < 32; dd++) {
        const int d = wid*32 + dd;
        uint2 u;
        u.x = h2_to_u32(__floats2half2_rn(stg[(lane*4+0)*VST + d], stg[(lane*4+1)*VST + d]));
        u.y = h2_to_u32(__floats2half2_rn(stg[(lane*4+2)*VST + d], stg[(lane*4+3)*VST + d]));
        *(uint2*)&Yt[(size_t)d*NL + tok0 + lane*4] = u;
    }
}

// PV epilogue: cross-warp LayerNorm over 256 cols, then fp32 store.
__device__ __forceinline__ void ln_epilogue(float c[4][8][4], float* red,
                                            const float* __restrict__ gamma,
                                            const float* __restrict__ beta,
                                            float* __restrict__ Y,
                                            int wm, int wn, int lane, int tid, int wid)
{
    const int g = lane >> 2, tg = lane & 3;
    const int wg = wid >> 1;
    __syncthreads();
    red[1280 + tid] = gamma[tid];
    red[1536 + tid] = beta[tid];
    #pragma unroll
    for (int i = 0; i < 4; i++) {
        const int rl = wm + i*16 + g;
        float s0 = 0.f, q0 = 0.f, s1 = 0.f, q1 = 0.f;
        #pragma unroll
        for (int j = 0; j < 8; j++) {
            s0 += c[i][j][0] + c[i][j][1];
            q0 += c[i][j][0]*c[i][j][0] + c[i][j][1]*c[i][j][1];
            s1 += c[i][j][2] + c[i][j][3];
            q1 += c[i][j][2]*c[i][j][2] + c[i][j][3]*c[i][j][3];
        }
        #pragma unroll
        for (int o = 1; o < 4; o <<= 1) {
            s0 += __shfl_xor_sync(0xffffffffu, s0, o);
            q0 += __shfl_xor_sync(0xffffffffu, q0, o);
            s1 += __shfl_xor_sync(0xffffffffu, s1, o);
            q1 += __shfl_xor_sync(0xffffffffu, q1, o);
        }
        if (tg == 0) {
            red[wg*128 + rl]       = s0; red[512 + wg*128 + rl]     = q0;
            red[wg*128 + rl + 8]   = s1; red[512 + wg*128 + rl + 8] = q1;
        }
    }
    __syncthreads();
    if (tid < 128) {
        float s = red[tid] + red[128+tid] + red[256+tid] + red[384+tid];
        float q = red[512+tid] + red[640+tid] + red[768+tid] + red[896+tid];
        float mean = s * (1.f/256.f);
        red[1024 + tid] = mean;
        red[1152 + tid] = rsqrtf(q * (1.f/256.f) - mean*mean + 1e-5f);
    }
    __syncthreads();
    #pragma unroll
    for (int i = 0; i < 4; i++) {
        const int rl = wm + i*16 + g;
        const float m0v = red[1024 + rl],     rs0 = red[1152 + rl];
        const float m1v = red[1024 + rl + 8], rs1 = red[1152 + rl + 8];
        #pragma unroll
        for (int j = 0; j < 8; j++) {
            const int col = wn + j*8 + tg*2;
            const float ga0 = red[1280 + col], ga1 = red[1281 + col];
            const float be0 = red[1536 + col], be1 = red[1537 + col];
            float2 v0 = make_float2((c[i][j][0]-m0v)*rs0*ga0 + be0,
                                    (c[i][j][1]-m0v)*rs0*ga1 + be1);
            float2 v1 = make_float2((c[i][j][2]-m1v)*rs1*ga0 + be0,
                                    (c[i][j][3]-m1v)*rs1*ga1 + be1);
            *(float2*)&Y[(size_t)rl*ND + col]     = v0;
            *(float2*)&Y[(size_t)(rl+8)*ND + col] = v1;
        }
    }
}

// ============================================================
// Kernel 1: projections (tf32 mainloop, fp16 outputs).  grid=(128, 6)
// ============================================================
__global__ __launch_bounds__(256, 1) void proj_mma(
    const float* __restrict__ q_real, const float* __restrict__ q_imag,
    const float* __restrict__ k_real, const float* __restrict__ k_imag,
    const float* __restrict__ v_real, const float* __restrict__ v_imag,
    const float* __restrict__ Wq, const float* __restrict__ bq,
    const float* __restrict__ Wk, const float* __restrict__ bk,
    const float* __restrict__ Wv, const float* __restrict__ bv)
{
    extern __shared__ float smf[];
    const uint32_t sb = smem_u32(smf);
    const int tid = threadIdx.x, lane = tid & 31, wid = tid >> 5;
    const int wm = (wid & 1)*64, wn = (wid >> 1)*64;
    const int m0 = blockIdx.x*128, z = blockIdx.y;
    const float *X, *W, *bias; __half* Y;
    switch (z) {
      case 0: X=q_real; W=Wq; bias=bq; Y=h_qr; break;
      case 1: X=q_imag; W=Wq; bias=bq; Y=h_qi; break;
      case 2: X=k_real; W=Wk; bias=bk; Y=h_kr; break;
      case 3: X=k_imag; W=Wk; bias=bk; Y=h_ki; break;
      case 4: X=v_real; W=Wv; bias=bv; Y=h_vrt; break;
      default: X=v_imag; W=Wv; bias=bv; Y=h_vit; break;
    }
    const float* Ab = X + (size_t)m0*ND;
    const int CH = 8;
    float c[4][8][4] = {};
    #pragma unroll
    for (int s = 0; s < 3; s++) {
        cpasyncA(sb + s*BUF_F*4, Ab + s*32, ND, tid);
        cpasyncB(sb + (s*BUF_F + ATILE_F)*4, W + s*32, ND, tid);
        CP_COMMIT;
    }
    #pragma unroll 1
    for (int ch = 0; ch < CH; ch++) {
        PIPE_WAIT(ch, CH);
        __syncthreads();
        if (ch + 3 < CH) {
            const int s = (ch+3) & 3;
            cpasyncA(sb + s*BUF_F*4, Ab + (ch+3)*32, ND, tid);
            cpasyncB(sb + (s*BUF_F + ATILE_F)*4, W + (ch+3)*32, ND, tid);
            CP_COMMIT;
        }
        float* base = smf + (ch & 3)*BUF_F;
        mma_block_raw(base, base + ATILE_F, c, wm, wn, lane);
    }
    if (z < 4) {
        epilogueQK(c, Y, ND, m0, wm, wn, lane, bias);
    } else {
        const int b = m0 >> 12, tok0 = m0 & (NL - 1);
        vt_epilogue(c, smf, bias, Y + (size_t)b*ND*NL, tok0, wm, wn, lane, wid);
    }
}

// ============================================================
// Kernel 2: scores (fp16, f16 accum — full rate).  grid=(16, 32, 4)
// K=512 (8 chunks of 64)
// ============================================================
__global__ __launch_bounds__(256, 1) void scores_mma()
{
    extern __shared__ __half smh[];
    const uint32_t sb = smem_u32(smh);
    const int tid = threadIdx.x, lane = tid & 31, wid = tid >> 5;
    const int wm = (wid & 1)*64, wn = (wid >> 1)*64;
    const int n0 = blockIdx.x*256, m0 = blockIdx.y*128, b = blockIdx.z;
    const __half* APh[2] = { h_qr + (size_t)(b*NL + m0)*ND, h_qi + (size_t)(b*NL + m0)*ND };
    const __half* BPh[2] = { h_kr + (size_t)(b*NL + n0)*ND, h_ki + (size_t)(b*NL + n0)*ND };
    const int CH = 8;                 // phase = ch>>2, k0 = (ch&3)*64
    uint32_t c[4][8][2] = {};         // f16x2 accumulators (zero = +0)
    #pragma unroll
    for (int s = 0; s < 3; s++) {
        cpasyncAH(sb + s*BUF_H*2, APh[0] + s*64, ND, tid);
        cpasyncBH(sb + (s*BUF_H + ATILE_H)*2, BPh[0] + s*64, ND, tid);
        CP_COMMIT;
    }
    #pragma unroll 1
    for (int ch = 0; ch < CH; ch++) {
        PIPE_WAIT(ch, CH);
        __syncthreads();
        if (ch + 3 < CH) {
            const int nc = ch + 3, s = nc & 3;
            cpasyncAH(sb + s*BUF_H*2, APh[nc >> 2] + (nc & 3)*64, ND, tid);
            cpasyncBH(sb + (s*BUF_H + ATILE_H)*2, BPh[nc >> 2] + (nc & 3)*64, ND, tid);
            CP_COMMIT;
        }
        const uint32_t* base = (const uint32_t*)(smh + (ch & 3)*BUF_H);
        mma_block_h16(base, base + ATILE_H/2, c, wm, wn, lane);
    }
    epilogueS16(c, h_s + (size_t)b*NL*NL, NL, m0, n0, wm, wn, lane);
}

// ============================================================
// Kernel 3: softmax on fp16 scores; writes fp16 probs
// ============================================================
__global__ __launch_bounds__(256) void softmax_kernel(const unsigned char* __restrict__ mask)
{
    __shared__ float sh[8];
    const int row = blockIdx.x, b = row >> 12, t = threadIdx.x;
    __half* S = h_s + (size_t)row * NL;
    const unsigned char* m = mask + (size_t)b * NL;
    float v[16];
    #pragma unroll
    for (int j = 0; j < 4; j++) {
        int f4 = t + j*256;
        uint2 x = *(const uint2*)&S[f4*4];
        float2 f0 = __half22float2(u32_to_h2(x.x));
        float2 f1 = __half22float2(u32_to_h2(x.y));
        uchar4 mk = *(const uchar4*)&m[f4*4];
        v[j*4+0] = mk.x ? -INFINITY : f0.x;
        v[j*4+1] = mk.y ? -INFINITY : f0.y;
        v[j*4+2] = mk.z ? -INFINITY : f1.x;
        v[j*4+3] = mk.w ? -INFINITY : f1.y;
    }
    float mx = -INFINITY;
    #pragma unroll
    for (int i = 0; i < 16; i++) mx = fmaxf(mx, v[i]);
    #pragma unroll
    for (int o = 16; o > 0; o >>= 1) mx = fmaxf(mx, __shfl_xor_sync(0xffffffffu, mx, o));
    if ((t & 31) == 0) sh[t >> 5] = mx;
    __syncthreads();
    mx = sh[0];
    #pragma unroll
    for (int i = 1; i < 8; i++) mx = fmaxf(mx, sh[i]);
    __syncthreads();
    float sum = 0.f;
    #pragma unroll
    for (int i = 0; i < 16; i++) { v[i] = __expf(v[i] - mx); sum += v[i]; }
    #pragma unroll
    for (int o = 16; o > 0; o >>= 1) sum += __shfl_xor_sync(0xffffffffu, sum, o);
    if ((t & 31) == 0) sh[t >> 5] = sum;
    __syncthreads();
    sum = 0.f;
    #pragma unroll
    for (int i = 0; i < 8; i++) sum += sh[i];
    const float inv = 1.f / sum;
    #pragma unroll
    for (int j = 0; j < 4; j++) {
        int f4 = t + j*256;
        uint2 o;
        o.x = h2_to_u32(__floats2half2_rn(v[j*4+0]*inv, v[j*4+1]*inv));
        o.y = h2_to_u32(__floats2half2_rn(v[j*4+2]*inv, v[j*4+3]*inv));
        *(uint2*)&S[f4*4] = o;
    }
}

// ============================================================
// Kernel 4: PV (fp16, f32 accum) + fused LayerNorm.  grid=(2, 32, 4)
// K=4096 (64 chunks of 64)
// ============================================================
__global__ __launch_bounds__(256, 1) void pv_mma(
    const float* __restrict__ gamma, const float* __restrict__ beta,
    float* __restrict__ out)
{
    extern __shared__ __half smh[];
    const uint32_t sb = smem_u32(smh);
    const int tid = threadIdx.x, lane = tid & 31, wid = tid >> 5;
    const int wm = (wid & 1)*64, wn = (wid >> 1)*64;
    const int stream = blockIdx.x, m0 = blockIdx.y*128, b = blockIdx.z;
    const __half* Ab = h_s + (size_t)(b*NL + m0)*NL;
    const __half* Bb = (stream ? h_vit : h_vrt) + (size_t)b*ND*NL;
    float* Y = out + (size_t)stream*BLD + (size_t)(b*NL + m0)*ND;
    const int CH = 64;
    float c[4][8][4] = {};
    #pragma unroll
    for (int s = 0; s < 3; s++) {
        cpasyncAH(sb + s*BUF_H*2, Ab + s*64, NL, tid);
        cpasyncBH(sb + (s*BUF_H + ATILE_H)*2, Bb + s*64, NL, tid);
        CP_COMMIT;
    }
    #pragma unroll 1
    for (int ch = 0; ch < CH; ch++) {
        PIPE_WAIT(ch, CH);
        __syncthreads();
        if (ch + 3 < CH) {
            const int s = (ch+3) & 3;
            cpasyncAH(sb + s*BUF_H*2, Ab + (ch+3)*64, NL, tid);
            cpasyncBH(sb + (s*BUF_H + ATILE_H)*2, Bb + (ch+3)*64, NL, tid);
            CP_COMMIT;
        }
        const uint32_t* base = (const uint32_t*)(smh + (ch & 3)*BUF_H);
        mma_block_h(base, base + ATILE_H/2, c, wm, wn, lane);
    }
    ln_epilogue(c, (float*)smh, gamma, beta, Y, wm, wn, lane, tid, wid);
}

// ============================================================
extern "C" void kernel_launch(void* const* d_in, const int* in_sizes, int n_in,
                              void* d_out, int out_size)
{
    (void)in_sizes; (void)n_in; (void)out_size;
    const float* q_real = (const float*)d_in[0];
    const float* q_imag = (const float*)d_in[1];
    const float* k_real = (const float*)d_in[2];
    const float* k_imag = (const float*)d_in[3];
    const float* v_real = (const float*)d_in[4];
    const float* v_imag = (const float*)d_in[5];
    const unsigned char* pad_mask = (const unsigned char*)d_in[6];
    const float* Wq = (const float*)d_in[7];
    const float* bq = (const float*)d_in[8];
    const float* Wk = (const float*)d_in[9];
    const float* bk = (const float*)d_in[10];
    const float* Wv = (const float*)d_in[11];
    const float* bv = (const float*)d_in[12];
    const float* gamma = (const float*)d_in[13];
    const float* beta  = (const float*)d_in[14];
    float* out = (float*)d_out;

    cudaFuncSetAttribute(proj_mma,   cudaFuncAttributeMaxDynamicSharedMemorySize, SMEM_P);
    cudaFuncSetAttribute(scores_mma, cudaFuncAttributeMaxDynamicSharedMemorySize, SMEM_H);
    cudaFuncSetAttribute(pv_mma,     cudaFuncAttributeMaxDynamicSharedMemorySize, SMEM_H);

    proj_mma<<<dim3(128, 6), 256, SMEM_P>>>(q_real, q_imag, k_real, k_imag,
                                            v_real, v_imag, Wq, bq, Wk, bk, Wv, bv);
    scores_mma<<<dim3(16, 32, NB), 256, SMEM_H>>>();
    softmax_kernel<<<NB*NL, 256>>>(pad_mask);
    pv_mma<<<dim3(2, 32, NB), 256, SMEM_H>>>(gamma, beta, out);
}